// round 3
// baseline (speedup 1.0000x reference)
#include <cuda_runtime.h>
#include <math.h>

// Problem dims (fixed by the reference)
#define Dh     256
#define Qn     64
#define Pn     128
#define Bn     64
#define TWO_D  512
#define FOUR_D 1024
#define LDW    33280   // (Q+1)*2D, row stride of W_ih

// ---------------- scratch (device globals: no allocation allowed) ----------------
__device__ float d_ga  [Qn * Bn * Dh];          //  4 MB  ga[q*B+b][d]   (gemm layout)
__device__ float d_gaB [Bn * Qn * Dh];          //  4 MB  gaB[b][q][d]   (seq layout)
__device__ float d_Spre[Pn * Bn * Dh];          //  8 MB  S_pre[t*B+b][d]
__device__ float d_Gp  [Pn * Bn * FOUR_D];      // 32 MB  Gp[t*B+b][j] (includes b_ih+b_hh)
__device__ float d_U   [Qn * Bn * FOUR_D];      // 16 MB  U[q*B+b][j]  (gemm layout)
__device__ float d_UB  [Bn * Qn * FOUR_D];      // 16 MB  UB[b][q][j]  (seq layout)
__device__ float d_WhhT[Dh * FOUR_D];           //  1 MB  WhhT[e][j]
__device__ float d_WbT [Dh * Dh];               // 256 KB WbT[e][d]
__device__ float d_bsum[FOUR_D];

// ---------------- tiny prep kernels (reference globals directly) ----------------
__global__ void bias_sum_kernel(const float* __restrict__ b_ih,
                                const float* __restrict__ b_hh) {
    int i = threadIdx.x + blockIdx.x * blockDim.x;
    if (i < FOUR_D) d_bsum[i] = b_ih[i] + b_hh[i];
}

__global__ void transpose_whh_kernel(const float* __restrict__ W_hh) {
    int e = blockIdx.x;                       // 0..255
    for (int j = threadIdx.x; j < FOUR_D; j += blockDim.x)
        d_WhhT[e * FOUR_D + j] = W_hh[j * Dh + e];
}

__global__ void transpose_wb_kernel(const float* __restrict__ Wb) {
    int e = blockIdx.x;                       // 0..255
    for (int d = threadIdx.x; d < Dh; d += blockDim.x)
        d_WbT[e * Dh + d] = Wb[d * Dh + e];
}

// rearrange ga [q*B+b][d] -> gaB [b][q][d], output-coalesced
__global__ void rearrange_ga_kernel() {
    long o = (long)blockIdx.x * blockDim.x + threadIdx.x;   // over B*Q*D
    if (o >= (long)Bn * Qn * Dh) return;
    int d = (int)(o % Dh);
    long bq = o / Dh;
    int q = (int)(bq % Qn);
    int b = (int)(bq / Qn);
    d_gaB[o] = d_ga[((long)(q * Bn + b)) * Dh + d];
}

// rearrange U [q*B+b][j] -> UB [b][q][j], output-coalesced
__global__ void rearrange_u_kernel() {
    long o = (long)blockIdx.x * blockDim.x + threadIdx.x;   // over B*Q*4D
    if (o >= (long)Bn * Qn * FOUR_D) return;
    int j = (int)(o % FOUR_D);
    long bq = o / FOUR_D;
    int q = (int)(bq % Qn);
    int b = (int)(bq / Qn);
    d_UB[o] = d_U[((long)(q * Bn + b)) * FOUR_D + j];
}

// ---------------- generic C = A * B^T (+bias), tiled fp32 ----------------
// A: M x K row-major (lda), B: N x K row-major (ldb) => C[m][n] = sum_k A[m,k]*B[n,k]
// BM=BN=64, BK=16, 256 threads, 4x4 per thread. Shared device body, thin wrappers.
__device__ __forceinline__ void gemm_abt64_body(
    const float* __restrict__ A, int lda,
    const float* __restrict__ Bm, int ldb,
    float* __restrict__ C, int ldc,
    int K, const float* __restrict__ bias)
{
    __shared__ float As[16][68];
    __shared__ float Bs[16][68];

    const int m0 = blockIdx.y * 64;
    const int n0 = blockIdx.x * 64;
    const int tid = threadIdx.x;
    const int tx = tid & 15;        // n-frag
    const int ty = tid >> 4;        // m-frag
    const int lr = tid >> 2;        // load row 0..63
    const int lk = (tid & 3) * 4;   // load k 0,4,8,12

    float acc[4][4];
#pragma unroll
    for (int i = 0; i < 4; i++)
#pragma unroll
        for (int j = 0; j < 4; j++) acc[i][j] = 0.f;

    for (int k0 = 0; k0 < K; k0 += 16) {
        float4 a4 = *(const float4*)&A [(long)(m0 + lr) * lda + k0 + lk];
        float4 b4 = *(const float4*)&Bm[(long)(n0 + lr) * ldb + k0 + lk];
        __syncthreads();
        As[lk + 0][lr] = a4.x; As[lk + 1][lr] = a4.y;
        As[lk + 2][lr] = a4.z; As[lk + 3][lr] = a4.w;
        Bs[lk + 0][lr] = b4.x; Bs[lk + 1][lr] = b4.y;
        Bs[lk + 2][lr] = b4.z; Bs[lk + 3][lr] = b4.w;
        __syncthreads();
#pragma unroll
        for (int kk = 0; kk < 16; kk++) {
            float4 av = *(const float4*)&As[kk][ty * 4];
            float4 bv = *(const float4*)&Bs[kk][tx * 4];
            acc[0][0] += av.x * bv.x; acc[0][1] += av.x * bv.y;
            acc[0][2] += av.x * bv.z; acc[0][3] += av.x * bv.w;
            acc[1][0] += av.y * bv.x; acc[1][1] += av.y * bv.y;
            acc[1][2] += av.y * bv.z; acc[1][3] += av.y * bv.w;
            acc[2][0] += av.z * bv.x; acc[2][1] += av.z * bv.y;
            acc[2][2] += av.z * bv.z; acc[2][3] += av.z * bv.w;
            acc[3][0] += av.w * bv.x; acc[3][1] += av.w * bv.y;
            acc[3][2] += av.w * bv.z; acc[3][3] += av.w * bv.w;
        }
    }

    float4 bb = make_float4(0.f, 0.f, 0.f, 0.f);
    if (bias) bb = *(const float4*)&bias[n0 + tx * 4];
#pragma unroll
    for (int i = 0; i < 4; i++) {
        long row = m0 + ty * 4 + i;
        float4 o;
        o.x = acc[i][0] + bb.x; o.y = acc[i][1] + bb.y;
        o.z = acc[i][2] + bb.z; o.w = acc[i][3] + bb.w;
        *(float4*)&C[row * ldc + n0 + tx * 4] = o;
    }
}

// wrappers: destinations are device globals referenced from device code
__global__ void __launch_bounds__(256)
k_gemm_ga(const float* __restrict__ H_q, const float* __restrict__ Wg) {
    gemm_abt64_body(H_q, TWO_D, Wg, TWO_D, d_ga, Dh, TWO_D, nullptr);
}
__global__ void __launch_bounds__(256)
k_gemm_spre(const float* __restrict__ H_p, const float* __restrict__ Wa,
            const float* __restrict__ ba) {
    gemm_abt64_body(H_p, TWO_D, Wa, TWO_D, d_Spre, Dh, TWO_D, ba);
}
__global__ void __launch_bounds__(256)
k_gemm_gp(const float* __restrict__ H_p, const float* __restrict__ W_ih) {
    gemm_abt64_body(H_p, TWO_D, W_ih, LDW, d_Gp, FOUR_D, TWO_D, d_bsum);
}
__global__ void __launch_bounds__(256)
k_gemm_u(const float* __restrict__ H_q, const float* __restrict__ W_ih) {
    long z = blockIdx.z;   // q index
    gemm_abt64_body(H_q + z * Bn * TWO_D, TWO_D,
                    W_ih + TWO_D + z * TWO_D, LDW,
                    d_U + z * Bn * FOUR_D, FOUR_D, TWO_D, nullptr);
}

// ---------------- sequential MatchLSTM: one block per batch element ----------------
__device__ __forceinline__ float sigmoidf_(float x) { return 1.f / (1.f + expf(-x)); }

__global__ void __launch_bounds__(256)
seq_kernel(const float* __restrict__ h0,      // h_ri [1,B,D]
           const float* __restrict__ c0,      // hidden [1,B,D] (zeros)
           const float* __restrict__ alpha_w, // [D]
           const float* __restrict__ alpha_b, // [1]
           float* __restrict__ out)           // [P,B,D]
{
    __shared__ float h_s[Dh];
    __shared__ float c_s[Dh];
    __shared__ float s_s[Dh];
    __shared__ float gates_s[FOUR_D];
    __shared__ float logit_s[Qn];
    __shared__ float alpha_s[Qn];
    __shared__ float aw_s[Dh];

    const int b    = blockIdx.x;
    const int tid  = threadIdx.x;
    const int warp = tid >> 5;
    const int lane = tid & 31;
    const float ab = alpha_b[0];

    const float* gaB = d_gaB + (long)b * Qn * Dh;   // [q][d] for this batch elem
    const float* UB  = d_UB  + (long)b * Qn * FOUR_D;

    aw_s[tid] = alpha_w[tid];
    h_s[tid]  = h0[b * Dh + tid];
    c_s[tid]  = c0[b * Dh + tid];
    __syncthreads();

    for (int t = 0; t < Pn; t++) {
        // ---- phase 1: s[d] = S_pre[t,b,d] + sum_e h[e]*Wb[d,e] (WbT coalesced) ----
        {
            float acc = d_Spre[((long)(t * Bn + b)) * Dh + tid];
#pragma unroll 8
            for (int e = 0; e < Dh; e++)
                acc += h_s[e] * d_WbT[e * Dh + tid];
            s_s[tid] = acc;
        }
        __syncthreads();

        // ---- phase 2: logits[q] = sum_d tanh(ga+s)*aw + ab; warp w -> q = w*8+qi ----
        for (int qi = 0; qi < 8; qi++) {
            int q = warp * 8 + qi;
            float sum = 0.f;
#pragma unroll
            for (int d0 = lane * 4; d0 < Dh; d0 += 128) {
                float4 g4 = *(const float4*)&gaB[q * Dh + d0];
                float4 s4 = *(const float4*)&s_s[d0];
                float4 a4 = *(const float4*)&aw_s[d0];
                sum += tanhf(g4.x + s4.x) * a4.x;
                sum += tanhf(g4.y + s4.y) * a4.y;
                sum += tanhf(g4.z + s4.z) * a4.z;
                sum += tanhf(g4.w + s4.w) * a4.w;
            }
#pragma unroll
            for (int o = 16; o > 0; o >>= 1)
                sum += __shfl_xor_sync(0xffffffffu, sum, o);
            if (lane == 0) logit_s[q] = sum + ab;
        }
        __syncthreads();

        // ---- phase 3: softmax over q (warp 0) ----
        if (warp == 0) {
            float l0 = logit_s[lane], l1 = logit_s[lane + 32];
            float m = fmaxf(l0, l1);
#pragma unroll
            for (int o = 16; o > 0; o >>= 1)
                m = fmaxf(m, __shfl_xor_sync(0xffffffffu, m, o));
            float e0 = expf(l0 - m), e1 = expf(l1 - m);
            float ssum = e0 + e1;
#pragma unroll
            for (int o = 16; o > 0; o >>= 1)
                ssum += __shfl_xor_sync(0xffffffffu, ssum, o);
            float inv = 1.f / ssum;
            alpha_s[lane]      = e0 * inv;
            alpha_s[lane + 32] = e1 * inv;
        }
        __syncthreads();

        // ---- phase 4: gates[j] = Gp + h@WhhT + sum_q alpha*U (thread -> 4 cols) ----
        {
            const int j4 = tid * 4;
            float4 acc4 = *(const float4*)&d_Gp[((long)(t * Bn + b)) * FOUR_D + j4];
#pragma unroll 4
            for (int e = 0; e < Dh; e++) {
                float hv = h_s[e];
                float4 w4 = *(const float4*)&d_WhhT[e * FOUR_D + j4];
                acc4.x += hv * w4.x; acc4.y += hv * w4.y;
                acc4.z += hv * w4.z; acc4.w += hv * w4.w;
            }
#pragma unroll 4
            for (int q = 0; q < Qn; q++) {
                float av = alpha_s[q];
                float4 u4 = *(const float4*)&UB[(long)q * FOUR_D + j4];
                acc4.x += av * u4.x; acc4.y += av * u4.y;
                acc4.z += av * u4.z; acc4.w += av * u4.w;
            }
            *(float4*)&gates_s[j4] = acc4;
        }
        __syncthreads();

        // ---- phase 5: LSTM pointwise; thread -> one d ----
        {
            float ig = gates_s[tid];
            float fg = gates_s[Dh + tid];
            float gg = gates_s[2 * Dh + tid];
            float og = gates_s[3 * Dh + tid];
            float cn = sigmoidf_(fg) * c_s[tid] + sigmoidf_(ig) * tanhf(gg);
            float hn = sigmoidf_(og) * tanhf(cn);
            c_s[tid] = cn;
            out[((long)t * Bn + b) * Dh + tid] = hn;
            h_s[tid] = hn;   // readers of old h synced above; next read after sync below
        }
        __syncthreads();
    }
}

// ---------------- launch: kernel launches ONLY, no other CUDA API ----------------
extern "C" void kernel_launch(void* const* d_in, const int* in_sizes, int n_in,
                              void* d_out, int out_size)
{
    const float* H_p     = (const float*)d_in[0];
    const float* h_ri    = (const float*)d_in[1];
    const float* H_q     = (const float*)d_in[2];
    const float* hidden  = (const float*)d_in[3];
    const float* Wa      = (const float*)d_in[4];
    const float* ba      = (const float*)d_in[5];
    const float* Wb      = (const float*)d_in[6];
    const float* Wg      = (const float*)d_in[7];
    const float* alpha_w = (const float*)d_in[8];
    const float* alpha_b = (const float*)d_in[9];
    const float* W_ih    = (const float*)d_in[10];
    const float* W_hh    = (const float*)d_in[11];
    const float* b_ih    = (const float*)d_in[12];
    const float* b_hh    = (const float*)d_in[13];
    float* out = (float*)d_out;

    // tiny prep
    bias_sum_kernel<<<4, 256>>>(b_ih, b_hh);
    transpose_whh_kernel<<<Dh, 256>>>(W_hh);
    transpose_wb_kernel<<<Dh, 256>>>(Wb);

    // precompute GEMMs (all K = 512)
    k_gemm_ga  <<<dim3(Dh / 64,     (Qn * Bn) / 64, 1),  256>>>(H_q, Wg);
    k_gemm_spre<<<dim3(Dh / 64,     (Pn * Bn) / 64, 1),  256>>>(H_p, Wa, ba);
    k_gemm_gp  <<<dim3(FOUR_D / 64, (Pn * Bn) / 64, 1),  256>>>(H_p, W_ih);
    k_gemm_u   <<<dim3(FOUR_D / 64, Bn / 64,       Qn),  256>>>(H_q, W_ih);

    // rearrange to batch-major for the sequential phase
    {
        long n1 = (long)Bn * Qn * Dh;      // 1,048,576
        long n2 = (long)Bn * Qn * FOUR_D;  // 4,194,304
        rearrange_ga_kernel<<<(unsigned)((n1 + 255) / 256), 256>>>();
        rearrange_u_kernel <<<(unsigned)((n2 + 255) / 256), 256>>>();
    }

    // sequential MatchLSTM (static smem only, ~11 KB)
    seq_kernel<<<Bn, 256>>>(h_ri, hidden, alpha_w, alpha_b, out);
}

// round 5
// speedup vs baseline: 2.2592x; 2.2592x over previous
#include <cuda_runtime.h>
#include <cuda_fp16.h>
#include <math.h>

// Problem dims (fixed by the reference)
#define Dh     256
#define Qn     64
#define Pn     128
#define Bn     64
#define TWO_D  512
#define FOUR_D 1024
#define LDW    33280   // (Q+1)*2D, row stride of W_ih

// ---------------- scratch (device globals: no allocation allowed) ----------------
__device__ float d_Spre[Pn * Bn * Dh];            //  8 MB  S_pre[t*B+b][d]
__device__ float d_Gp  [Pn * Bn * FOUR_D];        // 32 MB  Gp[t*B+b][j] (+ b_ih+b_hh)
__device__ float d_bsum[FOUR_D];

// fp16 packed recurrent streams
__device__ uint4 d_ga4 [Bn * Qn * Dh / 8];        //  2 MB  gah[b][q][d] half, uint4 = 8 d
__device__ uint4 d_Wh4 [64 * 512];                // 512 KB Wh4[e4][j][4e] half
__device__ uint2 d_Wb4 [64 * 256];                // 128 KB Wb4[e4][d][4e] half
__device__ uint4 d_U4  [Bn * 16 * 512];           //  8 MB  U4[b][q4][j][4q] half

__device__ __forceinline__ float2 h22f2(unsigned u) {
    __half2 h = *reinterpret_cast<__half2*>(&u);
    return __half22float2(h);
}

// ---------------- tiny prep kernels ----------------
__global__ void bias_sum_kernel(const float* __restrict__ b_ih,
                                const float* __restrict__ b_hh) {
    int i = threadIdx.x + blockIdx.x * blockDim.x;
    if (i < FOUR_D) d_bsum[i] = b_ih[i] + b_hh[i];
}

// W_hh [j][e] fp32 -> Wh4[e4][j][4] half  (j=0..1023, e4=0..63)
__global__ void pack_whh_kernel(const float* __restrict__ W_hh) {
    int idx = blockIdx.x * blockDim.x + threadIdx.x;   // 65536
    int e4 = idx & 63, j = idx >> 6;
    float4 w = *(const float4*)&W_hh[j * Dh + e4 * 4];
    __half2 h01 = __floats2half2_rn(w.x, w.y);
    __half2 h23 = __floats2half2_rn(w.z, w.w);
    uint2 v;
    v.x = *reinterpret_cast<unsigned*>(&h01);
    v.y = *reinterpret_cast<unsigned*>(&h23);
    ((uint2*)d_Wh4)[e4 * 1024 + j] = v;
}

// Wb [d][e] fp32 -> Wb4[e4][d][4] half
__global__ void pack_wb_kernel(const float* __restrict__ Wb) {
    int idx = blockIdx.x * blockDim.x + threadIdx.x;   // 16384
    int e4 = idx & 63, d = idx >> 6;
    float4 w = *(const float4*)&Wb[d * Dh + e4 * 4];
    __half2 h01 = __floats2half2_rn(w.x, w.y);
    __half2 h23 = __floats2half2_rn(w.z, w.w);
    uint2 v;
    v.x = *reinterpret_cast<unsigned*>(&h01);
    v.y = *reinterpret_cast<unsigned*>(&h23);
    d_Wb4[e4 * 256 + d] = v;
}

// ---------------- GEMM 64x64 tile body (proven) ----------------
// computes acc[4][4] for C[m0+ty*4+i][n0+tx*4+j] = sum_k A[m][k]*B[n][k]
#define GEMM64_PROLOG()                                                         \
    __shared__ float As[16][68];                                                \
    __shared__ float Bs[16][68];                                                \
    const int m0 = blockIdx.y * 64;                                             \
    const int n0 = blockIdx.x * 64;                                             \
    const int tid = threadIdx.x;                                                \
    const int tx = tid & 15;                                                    \
    const int ty = tid >> 4;                                                    \
    const int lr = tid >> 2;                                                    \
    const int lk = (tid & 3) * 4;                                               \
    float acc[4][4];                                                            \
    _Pragma("unroll") for (int i = 0; i < 4; i++)                               \
        _Pragma("unroll") for (int j = 0; j < 4; j++) acc[i][j] = 0.f;          \
    for (int k0 = 0; k0 < 512; k0 += 16) {                                      \
        float4 a4 = *(const float4*)&A [(long)(m0 + lr) * lda + k0 + lk];       \
        float4 b4 = *(const float4*)&Bm[(long)(n0 + lr) * ldb + k0 + lk];       \
        __syncthreads();                                                        \
        As[lk + 0][lr] = a4.x; As[lk + 1][lr] = a4.y;                           \
        As[lk + 2][lr] = a4.z; As[lk + 3][lr] = a4.w;                           \
        Bs[lk + 0][lr] = b4.x; Bs[lk + 1][lr] = b4.y;                           \
        Bs[lk + 2][lr] = b4.z; Bs[lk + 3][lr] = b4.w;                           \
        __syncthreads();                                                        \
        _Pragma("unroll") for (int kk = 0; kk < 16; kk++) {                     \
            float4 av = *(const float4*)&As[kk][ty * 4];                        \
            float4 bv = *(const float4*)&Bs[kk][tx * 4];                        \
            acc[0][0] += av.x * bv.x; acc[0][1] += av.x * bv.y;                 \
            acc[0][2] += av.x * bv.z; acc[0][3] += av.x * bv.w;                 \
            acc[1][0] += av.y * bv.x; acc[1][1] += av.y * bv.y;                 \
            acc[1][2] += av.y * bv.z; acc[1][3] += av.y * bv.w;                 \
            acc[2][0] += av.z * bv.x; acc[2][1] += av.z * bv.y;                 \
            acc[2][2] += av.z * bv.z; acc[2][3] += av.z * bv.w;                 \
            acc[3][0] += av.w * bv.x; acc[3][1] += av.w * bv.y;                 \
            acc[3][2] += av.w * bv.z; acc[3][3] += av.w * bv.w;                 \
        }                                                                       \
    }

// ga = H_q @ Wg^T, epilogue writes half directly to gah[b][q][d]
__global__ void __launch_bounds__(256)
k_gemm_ga(const float* __restrict__ A, const float* __restrict__ Bm) {
    const int lda = TWO_D, ldb = TWO_D;
    GEMM64_PROLOG()
    __half* gah = (__half*)d_ga4;
#pragma unroll
    for (int i = 0; i < 4; i++) {
        int m = m0 + ty * 4 + i;       // m = q*64 + b
        int q = m >> 6, b = m & 63;
        __half2 p01 = __floats2half2_rn(acc[i][0], acc[i][1]);
        __half2 p23 = __floats2half2_rn(acc[i][2], acc[i][3]);
        uint2 v;
        v.x = *reinterpret_cast<unsigned*>(&p01);
        v.y = *reinterpret_cast<unsigned*>(&p23);
        *(uint2*)&gah[((b * Qn + q) * Dh) + n0 + tx * 4] = v;
    }
}

// U[q] = H_q[q] @ W_ih[:, (1+q)*2D:(2+q)*2D]^T, epilogue scatters to U4 half
__global__ void __launch_bounds__(256)
k_gemm_u(const float* __restrict__ Aq, const float* __restrict__ W_ih) {
    const int q = blockIdx.z;
    const float* A  = Aq + (long)q * Bn * TWO_D;
    const float* Bm = W_ih + TWO_D + (long)q * TWO_D;
    const int lda = TWO_D, ldb = LDW;
    GEMM64_PROLOG()
    __half* U4h = (__half*)d_U4;
    const int q4 = q >> 2, qp = q & 3;
#pragma unroll
    for (int i = 0; i < 4; i++) {
        int b = m0 + ty * 4 + i;       // m0 == 0 (grid.y = 1)
#pragma unroll
        for (int jj = 0; jj < 4; jj++) {
            long hidx = ((long)(b * 16 + q4) * FOUR_D + n0 + tx * 4 + jj) * 4 + qp;
            U4h[hidx] = __float2half_rn(acc[i][jj]);
        }
    }
}

// ---------------- GEMM 128x64 tile body (for the two big fp32 outputs) ----------------
__device__ __forceinline__ void gemm128_body(
    const float* __restrict__ A, int lda,
    const float* __restrict__ Bm, int ldb,
    float* __restrict__ C, int ldc, const float* __restrict__ bias)
{
    __shared__ float As[16][132];
    __shared__ float Bs[16][68];
    const int m0 = blockIdx.y * 128;
    const int n0 = blockIdx.x * 64;
    const int tid = threadIdx.x;
    const int tx = tid & 15;          // 4 cols
    const int ty = tid >> 4;          // 8 rows
    const int arow = tid >> 1, ak = (tid & 1) * 8;
    const int brow = tid >> 2, bk = (tid & 3) * 4;

    float acc[8][4];
#pragma unroll
    for (int i = 0; i < 8; i++)
#pragma unroll
        for (int j = 0; j < 4; j++) acc[i][j] = 0.f;

    for (int k0 = 0; k0 < 512; k0 += 16) {
        float4 a0 = *(const float4*)&A [(long)(m0 + arow) * lda + k0 + ak];
        float4 a1 = *(const float4*)&A [(long)(m0 + arow) * lda + k0 + ak + 4];
        float4 b4 = *(const float4*)&Bm[(long)(n0 + brow) * ldb + k0 + bk];
        __syncthreads();
        As[ak + 0][arow] = a0.x; As[ak + 1][arow] = a0.y;
        As[ak + 2][arow] = a0.z; As[ak + 3][arow] = a0.w;
        As[ak + 4][arow] = a1.x; As[ak + 5][arow] = a1.y;
        As[ak + 6][arow] = a1.z; As[ak + 7][arow] = a1.w;
        Bs[bk + 0][brow] = b4.x; Bs[bk + 1][brow] = b4.y;
        Bs[bk + 2][brow] = b4.z; Bs[bk + 3][brow] = b4.w;
        __syncthreads();
#pragma unroll
        for (int kk = 0; kk < 16; kk++) {
            float4 av0 = *(const float4*)&As[kk][ty * 8];
            float4 av1 = *(const float4*)&As[kk][ty * 8 + 4];
            float4 bv  = *(const float4*)&Bs[kk][tx * 4];
            acc[0][0] += av0.x * bv.x; acc[0][1] += av0.x * bv.y;
            acc[0][2] += av0.x * bv.z; acc[0][3] += av0.x * bv.w;
            acc[1][0] += av0.y * bv.x; acc[1][1] += av0.y * bv.y;
            acc[1][2] += av0.y * bv.z; acc[1][3] += av0.y * bv.w;
            acc[2][0] += av0.z * bv.x; acc[2][1] += av0.z * bv.y;
            acc[2][2] += av0.z * bv.z; acc[2][3] += av0.z * bv.w;
            acc[3][0] += av0.w * bv.x; acc[3][1] += av0.w * bv.y;
            acc[3][2] += av0.w * bv.z; acc[3][3] += av0.w * bv.w;
            acc[4][0] += av1.x * bv.x; acc[4][1] += av1.x * bv.y;
            acc[4][2] += av1.x * bv.z; acc[4][3] += av1.x * bv.w;
            acc[5][0] += av1.y * bv.x; acc[5][1] += av1.y * bv.y;
            acc[5][2] += av1.y * bv.z; acc[5][3] += av1.y * bv.w;
            acc[6][0] += av1.z * bv.x; acc[6][1] += av1.z * bv.y;
            acc[6][2] += av1.z * bv.z; acc[6][3] += av1.z * bv.w;
            acc[7][0] += av1.w * bv.x; acc[7][1] += av1.w * bv.y;
            acc[7][2] += av1.w * bv.z; acc[7][3] += av1.w * bv.w;
        }
    }

    float4 bb = make_float4(0.f, 0.f, 0.f, 0.f);
    if (bias) bb = *(const float4*)&bias[n0 + tx * 4];
#pragma unroll
    for (int i = 0; i < 8; i++) {
        long row = m0 + ty * 8 + i;
        float4 o;
        o.x = acc[i][0] + bb.x; o.y = acc[i][1] + bb.y;
        o.z = acc[i][2] + bb.z; o.w = acc[i][3] + bb.w;
        *(float4*)&C[row * ldc + n0 + tx * 4] = o;
    }
}

__global__ void __launch_bounds__(256)
k_gemm_spre(const float* __restrict__ H_p, const float* __restrict__ Wa,
            const float* __restrict__ ba) {
    gemm128_body(H_p, TWO_D, Wa, TWO_D, d_Spre, Dh, ba);
}
__global__ void __launch_bounds__(256)
k_gemm_gp(const float* __restrict__ H_p, const float* __restrict__ W_ih) {
    gemm128_body(H_p, TWO_D, W_ih, LDW, d_Gp, FOUR_D, d_bsum);
}

// ---------------- sequential MatchLSTM: 64 blocks x 512 threads ----------------
__device__ __forceinline__ float sigmoidf_(float x) { return 1.f / (1.f + expf(-x)); }

__global__ void __launch_bounds__(512)
seq_kernel(const float* __restrict__ h0,
           const float* __restrict__ c0,
           const float* __restrict__ alpha_w,
           const float* __restrict__ alpha_b,
           float* __restrict__ out)
{
    __shared__ float h_s[Dh];
    __shared__ float c_s[Dh];
    __shared__ float s_s[Dh];
    __shared__ float s_part[2][Dh];
    __shared__ float gates_s[FOUR_D];
    __shared__ float logit_s[Qn];
    __shared__ float alpha_s[Qn];
    __shared__ float aw_s[Dh];

    const int b    = blockIdx.x;
    const int tid  = threadIdx.x;
    const int warp = tid >> 5;
    const int lane = tid & 31;
    const float ab = alpha_b[0];

    const __half* gah = (const __half*)d_ga4 + (long)b * Qn * Dh;
    const uint4*  u4b = d_U4 + (long)b * 16 * 512;

    if (tid < Dh) {
        aw_s[tid] = alpha_w[tid];
        h_s[tid]  = h0[b * Dh + tid];
        c_s[tid]  = c0[b * Dh + tid];
    }
    __syncthreads();

    for (int t = 0; t < Pn; t++) {
        // ---- phase 1: s-partials over e-halves; thread (ec, dd) ----
        {
            const int dd = tid & 255, ec = tid >> 8;   // ec in {0,1}
            float acc = 0.f;
            const uint2* wb = d_Wb4 + ec * 32 * 256 + dd;
#pragma unroll 8
            for (int e4 = 0; e4 < 32; e4++) {
                uint2 w = wb[e4 * 256];
                float2 f01 = h22f2(w.x), f23 = h22f2(w.y);
                const int e = (ec * 32 + e4) * 4;
                acc += h_s[e] * f01.x + h_s[e + 1] * f01.y
                     + h_s[e + 2] * f23.x + h_s[e + 3] * f23.y;
            }
            s_part[ec][dd] = acc;
        }
        __syncthreads();
        if (tid < Dh)
            s_s[tid] = d_Spre[((long)(t * Bn + b)) * Dh + tid]
                     + s_part[0][tid] + s_part[1][tid];
        __syncthreads();

        // ---- phase 2: logits; 16 warps x 4 q, lane covers 8 d via uint4 ----
#pragma unroll
        for (int qi = 0; qi < 4; qi++) {
            const int q = warp * 4 + qi;
            const int d0 = lane * 8;
            uint4 g = *(const uint4*)&gah[(long)q * Dh + d0];
            float2 g0 = h22f2(g.x), g1 = h22f2(g.y),
                   g2 = h22f2(g.z), g3 = h22f2(g.w);
            float sum =
                tanhf(g0.x + s_s[d0    ]) * aw_s[d0    ] +
                tanhf(g0.y + s_s[d0 + 1]) * aw_s[d0 + 1] +
                tanhf(g1.x + s_s[d0 + 2]) * aw_s[d0 + 2] +
                tanhf(g1.y + s_s[d0 + 3]) * aw_s[d0 + 3] +
                tanhf(g2.x + s_s[d0 + 4]) * aw_s[d0 + 4] +
                tanhf(g2.y + s_s[d0 + 5]) * aw_s[d0 + 5] +
                tanhf(g3.x + s_s[d0 + 6]) * aw_s[d0 + 6] +
                tanhf(g3.y + s_s[d0 + 7]) * aw_s[d0 + 7];
#pragma unroll
            for (int o = 16; o > 0; o >>= 1)
                sum += __shfl_xor_sync(0xffffffffu, sum, o);
            if (lane == 0) logit_s[q] = sum + ab;
        }
        __syncthreads();

        // ---- phase 3: softmax over 64 q (warp 0) ----
        if (warp == 0) {
            float l0 = logit_s[lane], l1 = logit_s[lane + 32];
            float m = fmaxf(l0, l1);
#pragma unroll
            for (int o = 16; o > 0; o >>= 1)
                m = fmaxf(m, __shfl_xor_sync(0xffffffffu, m, o));
            float e0 = expf(l0 - m), e1 = expf(l1 - m);
            float ssum = e0 + e1;
#pragma unroll
            for (int o = 16; o > 0; o >>= 1)
                ssum += __shfl_xor_sync(0xffffffffu, ssum, o);
            float inv = 1.f / ssum;
            alpha_s[lane]      = e0 * inv;
            alpha_s[lane + 32] = e1 * inv;
        }
        __syncthreads();

        // ---- phase 4: gates; thread handles j = 2*tid, 2*tid+1 ----
        {
            const int jp = tid;
            float2 gp2 = *(const float2*)&d_Gp[((long)(t * Bn + b)) * FOUR_D + 2 * jp];
            float g0 = gp2.x, g1 = gp2.y;
#pragma unroll 8
            for (int e4 = 0; e4 < 64; e4++) {
                uint4 w = d_Wh4[e4 * 512 + jp];
                float2 a = h22f2(w.x), bb2 = h22f2(w.y),
                       cc = h22f2(w.z), dd2 = h22f2(w.w);
                const int e = 4 * e4;
                const float hv0 = h_s[e], hv1 = h_s[e + 1],
                            hv2 = h_s[e + 2], hv3 = h_s[e + 3];
                g0 += hv0 * a.x  + hv1 * a.y  + hv2 * bb2.x + hv3 * bb2.y;
                g1 += hv0 * cc.x + hv1 * cc.y + hv2 * dd2.x + hv3 * dd2.y;
            }
#pragma unroll 4
            for (int q4 = 0; q4 < 16; q4++) {
                uint4 w = u4b[q4 * 512 + jp];
                float2 a = h22f2(w.x), bb2 = h22f2(w.y),
                       cc = h22f2(w.z), dd2 = h22f2(w.w);
                const float a0 = alpha_s[4 * q4],     a1 = alpha_s[4 * q4 + 1],
                            a2 = alpha_s[4 * q4 + 2], a3 = alpha_s[4 * q4 + 3];
                g0 += a0 * a.x  + a1 * a.y  + a2 * bb2.x + a3 * bb2.y;
                g1 += a0 * cc.x + a1 * cc.y + a2 * dd2.x + a3 * dd2.y;
            }
            gates_s[2 * jp]     = g0;
            gates_s[2 * jp + 1] = g1;
        }
        __syncthreads();

        // ---- phase 5: LSTM pointwise; tid < 256 -> one d ----
        if (tid < Dh) {
            float ig = gates_s[tid];
            float fg = gates_s[Dh + tid];
            float gg = gates_s[2 * Dh + tid];
            float og = gates_s[3 * Dh + tid];
            float cn = sigmoidf_(fg) * c_s[tid] + sigmoidf_(ig) * tanhf(gg);
            float hn = sigmoidf_(og) * tanhf(cn);
            c_s[tid] = cn;
            out[((long)t * Bn + b) * Dh + tid] = hn;
            h_s[tid] = hn;
        }
        __syncthreads();
    }
}

// ---------------- launch: kernel launches ONLY ----------------
extern "C" void kernel_launch(void* const* d_in, const int* in_sizes, int n_in,
                              void* d_out, int out_size)
{
    const float* H_p     = (const float*)d_in[0];
    const float* h_ri    = (const float*)d_in[1];
    const float* H_q     = (const float*)d_in[2];
    const float* hidden  = (const float*)d_in[3];
    const float* Wa      = (const float*)d_in[4];
    const float* ba      = (const float*)d_in[5];
    const float* Wb      = (const float*)d_in[6];
    const float* Wg      = (const float*)d_in[7];
    const float* alpha_w = (const float*)d_in[8];
    const float* alpha_b = (const float*)d_in[9];
    const float* W_ih    = (const float*)d_in[10];
    const float* W_hh    = (const float*)d_in[11];
    const float* b_ih    = (const float*)d_in[12];
    const float* b_hh    = (const float*)d_in[13];
    float* out = (float*)d_out;

    // prep / packing
    bias_sum_kernel<<<4, 256>>>(b_ih, b_hh);
    pack_whh_kernel<<<256, 256>>>(W_hh);   // 64*1024 elems
    pack_wb_kernel <<<64, 256>>>(Wb);      // 64*256  elems

    // precompute GEMMs (K = 512)
    k_gemm_ga  <<<dim3(Dh / 64,     (Qn * Bn) / 64,  1),  256>>>(H_q, Wg);
    k_gemm_spre<<<dim3(Dh / 64,     (Pn * Bn) / 128, 1),  256>>>(H_p, Wa, ba);
    k_gemm_gp  <<<dim3(FOUR_D / 64, (Pn * Bn) / 128, 1),  256>>>(H_p, W_ih);
    k_gemm_u   <<<dim3(FOUR_D / 64, 1,               Qn), 256>>>(H_q, W_ih);

    // sequential MatchLSTM
    seq_kernel<<<Bn, 512>>>(h_ri, hidden, alpha_w, alpha_b, out);
}

// round 6
// speedup vs baseline: 2.4019x; 1.0631x over previous
#include <cuda_runtime.h>
#include <cuda_fp16.h>
#include <math.h>

// Problem dims (fixed by the reference)
#define Dh     256
#define Qn     64
#define Pn     128
#define Bn     64
#define TWO_D  512
#define FOUR_D 1024
#define LDW    33280   // (Q+1)*2D, row stride of W_ih

// ---------------- scratch (device globals: no allocation allowed) ----------------
__device__ float d_Spre[Pn * Bn * Dh];            //  8 MB  S_pre[t*B+b][d]
__device__ float d_Gp  [Pn * Bn * FOUR_D];        // 32 MB  Gp[t*B+b][j] (+ b_ih+b_hh)
__device__ float d_bsum[FOUR_D];

// fp16 packed recurrent streams
__device__ uint4 d_ga4 [Bn * Qn * Dh / 8];        //  2 MB  gah[b][q][d] half
__device__ uint4 d_Wh4 [64 * 512];                // 512 KB Wh4[e4][jp][{j0:e0..e3, j1:e0..e3}]
__device__ uint2 d_Wb4 [64 * 256];                // 128 KB Wb4[e4][d][4e]
__device__ uint4 d_U4  [Bn * 16 * 512];           //  8 MB  U4[b][q4][jp][..]

__device__ __forceinline__ float2 h22f2(unsigned u) {
    __half2 h = *reinterpret_cast<__half2*>(&u);
    return __half22float2(h);
}

// ---------------- cluster helpers ----------------
__device__ __forceinline__ unsigned smem_u32(const void* p) {
    unsigned a;
    asm("{ .reg .u64 t; cvta.to.shared.u64 t, %1; cvt.u32.u64 %0, t; }"
        : "=r"(a) : "l"(p));
    return a;
}
__device__ __forceinline__ unsigned mapa_u32(unsigned addr, unsigned rank) {
    unsigned r;
    asm("mapa.shared::cluster.u32 %0, %1, %2;" : "=r"(r) : "r"(addr), "r"(rank));
    return r;
}
__device__ __forceinline__ void stc_f32(unsigned addr, float v) {
    asm volatile("st.shared::cluster.f32 [%0], %1;" :: "r"(addr), "f"(v) : "memory");
}
__device__ __forceinline__ void stc_f32x2(unsigned addr, float v0, float v1) {
    asm volatile("st.shared::cluster.v2.f32 [%0], {%1, %2};"
                 :: "r"(addr), "f"(v0), "f"(v1) : "memory");
}
__device__ __forceinline__ unsigned ctarank_u32() {
    unsigned r; asm("mov.u32 %0, %%cluster_ctarank;" : "=r"(r)); return r;
}
#define CLUSTER_SYNC() do {                                          \
    asm volatile("barrier.cluster.arrive.aligned;" ::: "memory");    \
    asm volatile("barrier.cluster.wait.aligned;"   ::: "memory");    \
} while (0)

// ---------------- tiny prep kernels ----------------
__global__ void bias_sum_kernel(const float* __restrict__ b_ih,
                                const float* __restrict__ b_hh) {
    int i = threadIdx.x + blockIdx.x * blockDim.x;
    if (i < FOUR_D) d_bsum[i] = b_ih[i] + b_hh[i];
}

// W_hh [j][e] fp32 -> Wh4[e4][j][4] half  (j=0..1023, e4=0..63)
__global__ void pack_whh_kernel(const float* __restrict__ W_hh) {
    int idx = blockIdx.x * blockDim.x + threadIdx.x;   // 65536
    int e4 = idx & 63, j = idx >> 6;
    float4 w = *(const float4*)&W_hh[j * Dh + e4 * 4];
    __half2 h01 = __floats2half2_rn(w.x, w.y);
    __half2 h23 = __floats2half2_rn(w.z, w.w);
    uint2 v;
    v.x = *reinterpret_cast<unsigned*>(&h01);
    v.y = *reinterpret_cast<unsigned*>(&h23);
    ((uint2*)d_Wh4)[e4 * 1024 + j] = v;
}

// Wb [d][e] fp32 -> Wb4[e4][d][4] half
__global__ void pack_wb_kernel(const float* __restrict__ Wb) {
    int idx = blockIdx.x * blockDim.x + threadIdx.x;   // 16384
    int e4 = idx & 63, d = idx >> 6;
    float4 w = *(const float4*)&Wb[d * Dh + e4 * 4];
    __half2 h01 = __floats2half2_rn(w.x, w.y);
    __half2 h23 = __floats2half2_rn(w.z, w.w);
    uint2 v;
    v.x = *reinterpret_cast<unsigned*>(&h01);
    v.y = *reinterpret_cast<unsigned*>(&h23);
    d_Wb4[e4 * 256 + d] = v;
}

// ---------------- GEMM 64x64 tile body (proven) ----------------
#define GEMM64_PROLOG()                                                         \
    __shared__ float As[16][68];                                                \
    __shared__ float Bs[16][68];                                                \
    const int m0 = blockIdx.y * 64;                                             \
    const int n0 = blockIdx.x * 64;                                             \
    const int tid = threadIdx.x;                                                \
    const int tx = tid & 15;                                                    \
    const int ty = tid >> 4;                                                    \
    const int lr = tid >> 2;                                                    \
    const int lk = (tid & 3) * 4;                                               \
    float acc[4][4];                                                            \
    _Pragma("unroll") for (int i = 0; i < 4; i++)                               \
        _Pragma("unroll") for (int j = 0; j < 4; j++) acc[i][j] = 0.f;          \
    for (int k0 = 0; k0 < 512; k0 += 16) {                                      \
        float4 a4 = *(const float4*)&A [(long)(m0 + lr) * lda + k0 + lk];       \
        float4 b4 = *(const float4*)&Bm[(long)(n0 + lr) * ldb + k0 + lk];       \
        __syncthreads();                                                        \
        As[lk + 0][lr] = a4.x; As[lk + 1][lr] = a4.y;                           \
        As[lk + 2][lr] = a4.z; As[lk + 3][lr] = a4.w;                           \
        Bs[lk + 0][lr] = b4.x; Bs[lk + 1][lr] = b4.y;                           \
        Bs[lk + 2][lr] = b4.z; Bs[lk + 3][lr] = b4.w;                           \
        __syncthreads();                                                        \
        _Pragma("unroll") for (int kk = 0; kk < 16; kk++) {                     \
            float4 av = *(const float4*)&As[kk][ty * 4];                        \
            float4 bv = *(const float4*)&Bs[kk][tx * 4];                        \
            acc[0][0] += av.x * bv.x; acc[0][1] += av.x * bv.y;                 \
            acc[0][2] += av.x * bv.z; acc[0][3] += av.x * bv.w;                 \
            acc[1][0] += av.y * bv.x; acc[1][1] += av.y * bv.y;                 \
            acc[1][2] += av.y * bv.z; acc[1][3] += av.y * bv.w;                 \
            acc[2][0] += av.z * bv.x; acc[2][1] += av.z * bv.y;                 \
            acc[2][2] += av.z * bv.z; acc[2][3] += av.z * bv.w;                 \
            acc[3][0] += av.w * bv.x; acc[3][1] += av.w * bv.y;                 \
            acc[3][2] += av.w * bv.z; acc[3][3] += av.w * bv.w;                 \
        }                                                                       \
    }

// ga = H_q @ Wg^T, epilogue writes half directly to gah[b][q][d]
__global__ void __launch_bounds__(256)
k_gemm_ga(const float* __restrict__ A, const float* __restrict__ Bm) {
    const int lda = TWO_D, ldb = TWO_D;
    GEMM64_PROLOG()
    __half* gah = (__half*)d_ga4;
#pragma unroll
    for (int i = 0; i < 4; i++) {
        int m = m0 + ty * 4 + i;       // m = q*64 + b
        int q = m >> 6, b = m & 63;
        __half2 p01 = __floats2half2_rn(acc[i][0], acc[i][1]);
        __half2 p23 = __floats2half2_rn(acc[i][2], acc[i][3]);
        uint2 v;
        v.x = *reinterpret_cast<unsigned*>(&p01);
        v.y = *reinterpret_cast<unsigned*>(&p23);
        *(uint2*)&gah[((b * Qn + q) * Dh) + n0 + tx * 4] = v;
    }
}

// U[q] = H_q[q] @ W_ih[:, (1+q)*2D:(2+q)*2D]^T, epilogue scatters to U4 half
__global__ void __launch_bounds__(256)
k_gemm_u(const float* __restrict__ Aq, const float* __restrict__ W_ih) {
    const int q = blockIdx.z;
    const float* A  = Aq + (long)q * Bn * TWO_D;
    const float* Bm = W_ih + TWO_D + (long)q * TWO_D;
    const int lda = TWO_D, ldb = LDW;
    GEMM64_PROLOG()
    __half* U4h = (__half*)d_U4;
    const int q4 = q >> 2, qp = q & 3;
#pragma unroll
    for (int i = 0; i < 4; i++) {
        int b = m0 + ty * 4 + i;       // m0 == 0 (grid.y = 1)
#pragma unroll
        for (int jj = 0; jj < 4; jj++) {
            long hidx = ((long)(b * 16 + q4) * FOUR_D + n0 + tx * 4 + jj) * 4 + qp;
            U4h[hidx] = __float2half_rn(acc[i][jj]);
        }
    }
}

// ---------------- GEMM 128x64 tile body (two big fp32 outputs) ----------------
__device__ __forceinline__ void gemm128_body(
    const float* __restrict__ A, int lda,
    const float* __restrict__ Bm, int ldb,
    float* __restrict__ C, int ldc, const float* __restrict__ bias)
{
    __shared__ float As[16][132];
    __shared__ float Bs[16][68];
    const int m0 = blockIdx.y * 128;
    const int n0 = blockIdx.x * 64;
    const int tid = threadIdx.x;
    const int tx = tid & 15;
    const int ty = tid >> 4;
    const int arow = tid >> 1, ak = (tid & 1) * 8;
    const int brow = tid >> 2, bk = (tid & 3) * 4;

    float acc[8][4];
#pragma unroll
    for (int i = 0; i < 8; i++)
#pragma unroll
        for (int j = 0; j < 4; j++) acc[i][j] = 0.f;

    for (int k0 = 0; k0 < 512; k0 += 16) {
        float4 a0 = *(const float4*)&A [(long)(m0 + arow) * lda + k0 + ak];
        float4 a1 = *(const float4*)&A [(long)(m0 + arow) * lda + k0 + ak + 4];
        float4 b4 = *(const float4*)&Bm[(long)(n0 + brow) * ldb + k0 + bk];
        __syncthreads();
        As[ak + 0][arow] = a0.x; As[ak + 1][arow] = a0.y;
        As[ak + 2][arow] = a0.z; As[ak + 3][arow] = a0.w;
        As[ak + 4][arow] = a1.x; As[ak + 5][arow] = a1.y;
        As[ak + 6][arow] = a1.z; As[ak + 7][arow] = a1.w;
        Bs[bk + 0][brow] = b4.x; Bs[bk + 1][brow] = b4.y;
        Bs[bk + 2][brow] = b4.z; Bs[bk + 3][brow] = b4.w;
        __syncthreads();
#pragma unroll
        for (int kk = 0; kk < 16; kk++) {
            float4 av0 = *(const float4*)&As[kk][ty * 8];
            float4 av1 = *(const float4*)&As[kk][ty * 8 + 4];
            float4 bv  = *(const float4*)&Bs[kk][tx * 4];
            acc[0][0] += av0.x * bv.x; acc[0][1] += av0.x * bv.y;
            acc[0][2] += av0.x * bv.z; acc[0][3] += av0.x * bv.w;
            acc[1][0] += av0.y * bv.x; acc[1][1] += av0.y * bv.y;
            acc[1][2] += av0.y * bv.z; acc[1][3] += av0.y * bv.w;
            acc[2][0] += av0.z * bv.x; acc[2][1] += av0.z * bv.y;
            acc[2][2] += av0.z * bv.z; acc[2][3] += av0.z * bv.w;
            acc[3][0] += av0.w * bv.x; acc[3][1] += av0.w * bv.y;
            acc[3][2] += av0.w * bv.z; acc[3][3] += av0.w * bv.w;
            acc[4][0] += av1.x * bv.x; acc[4][1] += av1.x * bv.y;
            acc[4][2] += av1.x * bv.z; acc[4][3] += av1.x * bv.w;
            acc[5][0] += av1.y * bv.x; acc[5][1] += av1.y * bv.y;
            acc[5][2] += av1.y * bv.z; acc[5][3] += av1.y * bv.w;
            acc[6][0] += av1.z * bv.x; acc[6][1] += av1.z * bv.y;
            acc[6][2] += av1.z * bv.z; acc[6][3] += av1.z * bv.w;
            acc[7][0] += av1.w * bv.x; acc[7][1] += av1.w * bv.y;
            acc[7][2] += av1.w * bv.z; acc[7][3] += av1.w * bv.w;
        }
    }

    float4 bb = make_float4(0.f, 0.f, 0.f, 0.f);
    if (bias) bb = *(const float4*)&bias[n0 + tx * 4];
#pragma unroll
    for (int i = 0; i < 8; i++) {
        long row = m0 + ty * 8 + i;
        float4 o;
        o.x = acc[i][0] + bb.x; o.y = acc[i][1] + bb.y;
        o.z = acc[i][2] + bb.z; o.w = acc[i][3] + bb.w;
        *(float4*)&C[row * ldc + n0 + tx * 4] = o;
    }
}

__global__ void __launch_bounds__(256)
k_gemm_spre(const float* __restrict__ H_p, const float* __restrict__ Wa,
            const float* __restrict__ ba) {
    gemm128_body(H_p, TWO_D, Wa, TWO_D, d_Spre, Dh, ba);
}
__global__ void __launch_bounds__(256)
k_gemm_gp(const float* __restrict__ H_p, const float* __restrict__ W_ih) {
    gemm128_body(H_p, TWO_D, W_ih, LDW, d_Gp, FOUR_D, d_bsum);
}

// ---------------- sequential MatchLSTM: 2-CTA cluster per batch element ----------
// grid 128 = 64 clusters x 2 CTAs, 256 threads/CTA.
// CTA r owns d-half [r*128, r*128+128) for phases 1-2 and j-half [r*512,(r+1)*512)
// for phase 4. Exchanges per step: partial logits (256 B) + gate half (2 KB) via
// DSMEM, each followed by one cluster barrier. h/c replicated (identical fp math).
__device__ __forceinline__ float sigmoidf_(float x) { return 1.f / (1.f + expf(-x)); }

__global__ __launch_bounds__(256, 1) __cluster_dims__(2, 1, 1)
void seq_kernel(const float* __restrict__ h0,
                const float* __restrict__ c0,
                const float* __restrict__ alpha_w,
                const float* __restrict__ alpha_b,
                float* __restrict__ out)
{
    __shared__ __align__(16) float h_s[Dh];
    __shared__ __align__(16) float c_s[Dh];
    __shared__ __align__(16) float s_s[128];          // local d-half
    __shared__ __align__(16) float s_part[2][128];
    __shared__ __align__(16) float gates_s[FOUR_D];   // full (peer fills other half)
    __shared__ __align__(16) float logit_part[2][Qn]; // [half][q]
    __shared__ __align__(16) float alpha_s[Qn];
    __shared__ __align__(16) float aw_s[Dh];

    const int tid  = threadIdx.x;
    const int warp = tid >> 5;
    const int lane = tid & 31;
    const unsigned rank = ctarank_u32();   // == blockIdx.x & 1
    const unsigned peer = 1u - rank;
    const int r = (int)rank;
    const int b = blockIdx.x >> 1;
    const float ab = alpha_b[0];

    // peer smem bases (DSMEM window is linear: mapa base once, add offsets)
    const unsigned gates_peer = mapa_u32(smem_u32(gates_s), peer);
    const unsigned logit_peer = mapa_u32(smem_u32(&logit_part[r][0]), peer);

    const __half* gah = (const __half*)d_ga4 + (long)b * Qn * Dh;
    const uint4*  u4b = d_U4 + (long)b * 16 * 512;

    aw_s[tid] = alpha_w[tid];
    h_s[tid]  = h0[b * Dh + tid];
    c_s[tid]  = c0[b * Dh + tid];
    CLUSTER_SYNC();   // both CTAs initialized before any DSMEM traffic

    for (int t = 0; t < Pn; t++) {
        // ---- phase 1: s for local d-half; thread (ec, dd), dd in 0..127 ----
        {
            const int dd = tid & 127, ec = tid >> 7;   // ec in {0,1}
            const int d = r * 128 + dd;
            float acc = 0.f;
            const uint2* wb = d_Wb4 + ec * 32 * 256 + d;
#pragma unroll 8
            for (int i = 0; i < 32; i++) {
                uint2 w = wb[i * 256];
                float2 f01 = h22f2(w.x), f23 = h22f2(w.y);
                const int e = (ec * 32 + i) * 4;
                acc += h_s[e] * f01.x + h_s[e + 1] * f01.y
                     + h_s[e + 2] * f23.x + h_s[e + 3] * f23.y;
            }
            s_part[ec][dd] = acc;
        }
        __syncthreads();
        if (tid < 128)
            s_s[tid] = d_Spre[((long)(t * Bn + b)) * Dh + r * 128 + tid]
                     + s_part[0][tid] + s_part[1][tid];
        __syncthreads();

        // ---- phase 2: partial logits over local d-half; 8 warps x 8 q ----
#pragma unroll
        for (int qi = 0; qi < 8; qi++) {
            const int q = warp * 8 + qi;
            const int dl = lane * 4;              // local half index
            const int dg = r * 128 + dl;          // global d
            uint2 g = *(const uint2*)&gah[(long)q * Dh + dg];
            float2 g0 = h22f2(g.x), g1 = h22f2(g.y);
            float sum =
                tanhf(g0.x + s_s[dl    ]) * aw_s[dg    ] +
                tanhf(g0.y + s_s[dl + 1]) * aw_s[dg + 1] +
                tanhf(g1.x + s_s[dl + 2]) * aw_s[dg + 2] +
                tanhf(g1.y + s_s[dl + 3]) * aw_s[dg + 3];
#pragma unroll
            for (int o = 16; o > 0; o >>= 1)
                sum += __shfl_xor_sync(0xffffffffu, sum, o);
            if (lane == 0) {
                logit_part[r][q] = sum;               // local copy
                stc_f32(logit_peer + q * 4, sum);     // peer's logit_part[r][q]
            }
        }
        CLUSTER_SYNC();   // #1: partial logits visible in both CTAs

        // ---- phase 3: redundant softmax over 64 q (warp 0 of each CTA) ----
        if (warp == 0) {
            float l0 = logit_part[0][lane]      + logit_part[1][lane]      + ab;
            float l1 = logit_part[0][lane + 32] + logit_part[1][lane + 32] + ab;
            float m = fmaxf(l0, l1);
#pragma unroll
            for (int o = 16; o > 0; o >>= 1)
                m = fmaxf(m, __shfl_xor_sync(0xffffffffu, m, o));
            float e0 = expf(l0 - m), e1 = expf(l1 - m);
            float ssum = e0 + e1;
#pragma unroll
            for (int o = 16; o > 0; o >>= 1)
                ssum += __shfl_xor_sync(0xffffffffu, ssum, o);
            float inv = 1.f / ssum;
            alpha_s[lane]      = e0 * inv;
            alpha_s[lane + 32] = e1 * inv;
        }
        __syncthreads();

        // ---- phase 4: gates for local j-half; jp = r*256 + tid -> j = 2jp,2jp+1 --
        {
            const int jp = r * 256 + tid;
            float2 gp2 = *(const float2*)&d_Gp[((long)(t * Bn + b)) * FOUR_D + 2 * jp];
            float g0 = gp2.x, g1 = gp2.y;
#pragma unroll 8
            for (int e4 = 0; e4 < 64; e4++) {
                uint4 w = d_Wh4[e4 * 512 + jp];
                float2 a = h22f2(w.x), bb2 = h22f2(w.y),
                       cc = h22f2(w.z), dd2 = h22f2(w.w);
                const int e = 4 * e4;
                const float hv0 = h_s[e], hv1 = h_s[e + 1],
                            hv2 = h_s[e + 2], hv3 = h_s[e + 3];
                g0 += hv0 * a.x  + hv1 * a.y  + hv2 * bb2.x + hv3 * bb2.y;
                g1 += hv0 * cc.x + hv1 * cc.y + hv2 * dd2.x + hv3 * dd2.y;
            }
#pragma unroll 4
            for (int q4 = 0; q4 < 16; q4++) {
                uint4 w = u4b[q4 * 512 + jp];
                float2 a = h22f2(w.x), bb2 = h22f2(w.y),
                       cc = h22f2(w.z), dd2 = h22f2(w.w);
                const float a0 = alpha_s[4 * q4],     a1 = alpha_s[4 * q4 + 1],
                            a2 = alpha_s[4 * q4 + 2], a3 = alpha_s[4 * q4 + 3];
                g0 += a0 * a.x  + a1 * a.y  + a2 * bb2.x + a3 * bb2.y;
                g1 += a0 * cc.x + a1 * cc.y + a2 * dd2.x + a3 * dd2.y;
            }
            gates_s[2 * jp]     = g0;                      // local
            gates_s[2 * jp + 1] = g1;
            stc_f32x2(gates_peer + (2 * jp) * 4, g0, g1);  // peer's same slots
        }
        CLUSTER_SYNC();   // #2: full gate vector in both CTAs

        // ---- phase 5: redundant LSTM pointwise; d = tid (h,c stay replicated) ----
        {
            float ig = gates_s[tid];
            float fg = gates_s[Dh + tid];
            float gg = gates_s[2 * Dh + tid];
            float og = gates_s[3 * Dh + tid];
            float cn = sigmoidf_(fg) * c_s[tid] + sigmoidf_(ig) * tanhf(gg);
            float hn = sigmoidf_(og) * tanhf(cn);
            c_s[tid] = cn;
            h_s[tid] = hn;
            if ((tid >> 7) == r)                      // each CTA writes its d-half
                out[((long)t * Bn + b) * Dh + tid] = hn;
        }
        __syncthreads();   // h_s/c_s settled before next step's phase 1/4 reads
    }
}

// ---------------- launch: kernel launches ONLY ----------------
extern "C" void kernel_launch(void* const* d_in, const int* in_sizes, int n_in,
                              void* d_out, int out_size)
{
    const float* H_p     = (const float*)d_in[0];
    const float* h_ri    = (const float*)d_in[1];
    const float* H_q     = (const float*)d_in[2];
    const float* hidden  = (const float*)d_in[3];
    const float* Wa      = (const float*)d_in[4];
    const float* ba      = (const float*)d_in[5];
    const float* Wb      = (const float*)d_in[6];
    const float* Wg      = (const float*)d_in[7];
    const float* alpha_w = (const float*)d_in[8];
    const float* alpha_b = (const float*)d_in[9];
    const float* W_ih    = (const float*)d_in[10];
    const float* W_hh    = (const float*)d_in[11];
    const float* b_ih    = (const float*)d_in[12];
    const float* b_hh    = (const float*)d_in[13];
    float* out = (float*)d_out;

    // prep / packing
    bias_sum_kernel<<<4, 256>>>(b_ih, b_hh);
    pack_whh_kernel<<<256, 256>>>(W_hh);
    pack_wb_kernel <<<64, 256>>>(Wb);

    // precompute GEMMs (K = 512)
    k_gemm_ga  <<<dim3(Dh / 64,     (Qn * Bn) / 64,  1),  256>>>(H_q, Wg);
    k_gemm_spre<<<dim3(Dh / 64,     (Pn * Bn) / 128, 1),  256>>>(H_p, Wa, ba);
    k_gemm_gp  <<<dim3(FOUR_D / 64, (Pn * Bn) / 128, 1),  256>>>(H_p, W_ih);
    k_gemm_u   <<<dim3(FOUR_D / 64, 1,               Qn), 256>>>(H_q, W_ih);

    // sequential MatchLSTM: 64 clusters x 2 CTAs
    seq_kernel<<<2 * Bn, 256>>>(h_ri, hidden, alpha_w, alpha_b, out);
}

// round 9
// speedup vs baseline: 2.8699x; 1.1948x over previous
#include <cuda_runtime.h>
#include <cuda_fp16.h>
#include <math.h>

// Problem dims (fixed by the reference)
#define Dh     256
#define Qn     64
#define Pn     128
#define Bn     64
#define TWO_D  512
#define FOUR_D 1024
#define LDW    33280   // (Q+1)*2D, row stride of W_ih

// ---------------- scratch (device globals: no allocation allowed) ----------------
__device__ float d_Spre[Pn * Bn * Dh];            //  8 MB  S_pre[t*B+b][d]
__device__ float d_Gp  [Pn * Bn * FOUR_D];        // 32 MB  Gp[t*B+b][j] (+ b_ih+b_hh)
__device__ float d_bsum[FOUR_D];

// fp16 packed recurrent streams
__device__ uint4 d_ga4 [Bn * Qn * Dh / 8];        //  2 MB  gah[b][q][d] half
__device__ uint4 d_Wh4 [64 * 512];                // 512 KB Wh4[e4][jp][{j0:e0..e3, j1:e0..e3}]
__device__ uint2 d_Wb4 [64 * 256];                // 128 KB Wb4[e4][d][4e]
__device__ uint4 d_U4  [Bn * 16 * 512];           //  8 MB  U4[b][q4][jp][..]

__device__ __forceinline__ float2 h22f2(unsigned u) {
    __half2 h = *reinterpret_cast<__half2*>(&u);
    return __half22float2(h);
}
__device__ __forceinline__ __half2 u2h2(unsigned u) {
    return *reinterpret_cast<__half2*>(&u);
}
__device__ __forceinline__ float tanh_a(float x) {
    float y; asm("tanh.approx.f32 %0, %1;" : "=f"(y) : "f"(x)); return y;
}

// ---------------- cluster helpers (byte-identical pattern to passing R6) --------
__device__ __forceinline__ unsigned smem_u32(const void* p) {
    unsigned a;
    asm("{ .reg .u64 t; cvta.to.shared.u64 t, %1; cvt.u32.u64 %0, t; }"
        : "=r"(a) : "l"(p));
    return a;
}
__device__ __forceinline__ unsigned mapa_u32(unsigned addr, unsigned rank) {
    unsigned r;
    asm("mapa.shared::cluster.u32 %0, %1, %2;" : "=r"(r) : "r"(addr), "r"(rank));
    return r;
}
__device__ __forceinline__ void stc_f32(unsigned addr, float v) {
    asm volatile("st.shared::cluster.f32 [%0], %1;" :: "r"(addr), "f"(v) : "memory");
}
__device__ __forceinline__ void stc_f32x2(unsigned addr, float v0, float v1) {
    asm volatile("st.shared::cluster.v2.f32 [%0], {%1, %2};"
                 :: "r"(addr), "f"(v0), "f"(v1) : "memory");
}
__device__ __forceinline__ unsigned ctarank_u32() {
    unsigned r; asm("mov.u32 %0, %%cluster_ctarank;" : "=r"(r)); return r;
}
#define CLUSTER_SYNC() do {                                          \
    asm volatile("barrier.cluster.arrive.aligned;" ::: "memory");    \
    asm volatile("barrier.cluster.wait.aligned;"   ::: "memory");    \
} while (0)

// ---------------- merged prep kernel (one launch) ----------------
__global__ void prep_kernel(const float* __restrict__ b_ih,
                            const float* __restrict__ b_hh,
                            const float* __restrict__ W_hh,
                            const float* __restrict__ Wb) {
    int idx = blockIdx.x * blockDim.x + threadIdx.x;   // 65536
    // W_hh [j][e] fp32 -> Wh4[e4][j][4] half
    {
        int e4 = idx & 63, j = idx >> 6;
        float4 w = *(const float4*)&W_hh[j * Dh + e4 * 4];
        __half2 h01 = __floats2half2_rn(w.x, w.y);
        __half2 h23 = __floats2half2_rn(w.z, w.w);
        uint2 v;
        v.x = *reinterpret_cast<unsigned*>(&h01);
        v.y = *reinterpret_cast<unsigned*>(&h23);
        ((uint2*)d_Wh4)[e4 * 1024 + j] = v;
    }
    // Wb [d][e] fp32 -> Wb4[e4][d][4] half
    if (idx < 16384) {
        int e4 = idx & 63, d = idx >> 6;
        float4 w = *(const float4*)&Wb[d * Dh + e4 * 4];
        __half2 h01 = __floats2half2_rn(w.x, w.y);
        __half2 h23 = __floats2half2_rn(w.z, w.w);
        uint2 v;
        v.x = *reinterpret_cast<unsigned*>(&h01);
        v.y = *reinterpret_cast<unsigned*>(&h23);
        d_Wb4[e4 * 256 + d] = v;
    }
    if (idx < FOUR_D) d_bsum[idx] = b_ih[idx] + b_hh[idx];
}

// ---------------- GEMM 64x64 tile body (proven) ----------------
#define GEMM64_PROLOG()                                                         \
    __shared__ float As[16][68];                                                \
    __shared__ float Bs[16][68];                                                \
    const int m0 = blockIdx.y * 64;                                             \
    const int n0 = blockIdx.x * 64;                                             \
    const int tid = threadIdx.x;                                                \
    const int tx = tid & 15;                                                    \
    const int ty = tid >> 4;                                                    \
    const int lr = tid >> 2;                                                    \
    const int lk = (tid & 3) * 4;                                               \
    float acc[4][4];                                                            \
    _Pragma("unroll") for (int i = 0; i < 4; i++)                               \
        _Pragma("unroll") for (int j = 0; j < 4; j++) acc[i][j] = 0.f;          \
    for (int k0 = 0; k0 < 512; k0 += 16) {                                      \
        float4 a4 = *(const float4*)&A [(long)(m0 + lr) * lda + k0 + lk];       \
        float4 b4 = *(const float4*)&Bm[(long)(n0 + lr) * ldb + k0 + lk];       \
        __syncthreads();                                                        \
        As[lk + 0][lr] = a4.x; As[lk + 1][lr] = a4.y;                           \
        As[lk + 2][lr] = a4.z; As[lk + 3][lr] = a4.w;                           \
        Bs[lk + 0][lr] = b4.x; Bs[lk + 1][lr] = b4.y;                           \
        Bs[lk + 2][lr] = b4.z; Bs[lk + 3][lr] = b4.w;                           \
        __syncthreads();                                                        \
        _Pragma("unroll") for (int kk = 0; kk < 16; kk++) {                     \
            float4 av = *(const float4*)&As[kk][ty * 4];                        \
            float4 bv = *(const float4*)&Bs[kk][tx * 4];                        \
            acc[0][0] += av.x * bv.x; acc[0][1] += av.x * bv.y;                 \
            acc[0][2] += av.x * bv.z; acc[0][3] += av.x * bv.w;                 \
            acc[1][0] += av.y * bv.x; acc[1][1] += av.y * bv.y;                 \
            acc[1][2] += av.y * bv.z; acc[1][3] += av.y * bv.w;                 \
            acc[2][0] += av.z * bv.x; acc[2][1] += av.z * bv.y;                 \
            acc[2][2] += av.z * bv.z; acc[2][3] += av.z * bv.w;                 \
            acc[3][0] += av.w * bv.x; acc[3][1] += av.w * bv.y;                 \
            acc[3][2] += av.w * bv.z; acc[3][3] += av.w * bv.w;                 \
        }                                                                       \
    }

// ga = H_q @ Wg^T, epilogue writes half directly to gah[b][q][d]
__global__ void __launch_bounds__(256)
k_gemm_ga(const float* __restrict__ A, const float* __restrict__ Bm) {
    const int lda = TWO_D, ldb = TWO_D;
    GEMM64_PROLOG()
    __half* gah = (__half*)d_ga4;
#pragma unroll
    for (int i = 0; i < 4; i++) {
        int m = m0 + ty * 4 + i;       // m = q*64 + b
        int q = m >> 6, b = m & 63;
        __half2 p01 = __floats2half2_rn(acc[i][0], acc[i][1]);
        __half2 p23 = __floats2half2_rn(acc[i][2], acc[i][3]);
        uint2 v;
        v.x = *reinterpret_cast<unsigned*>(&p01);
        v.y = *reinterpret_cast<unsigned*>(&p23);
        *(uint2*)&gah[((b * Qn + q) * Dh) + n0 + tx * 4] = v;
    }
}

// U[q] = H_q[q] @ W_ih[:, (1+q)*2D:(2+q)*2D]^T, epilogue scatters to U4 half
__global__ void __launch_bounds__(256)
k_gemm_u(const float* __restrict__ Aq, const float* __restrict__ W_ih) {
    const int q = blockIdx.z;
    const float* A  = Aq + (long)q * Bn * TWO_D;
    const float* Bm = W_ih + TWO_D + (long)q * TWO_D;
    const int lda = TWO_D, ldb = LDW;
    GEMM64_PROLOG()
    __half* U4h = (__half*)d_U4;
    const int q4 = q >> 2, qp = q & 3;
#pragma unroll
    for (int i = 0; i < 4; i++) {
        int b = m0 + ty * 4 + i;       // m0 == 0 (grid.y = 1)
#pragma unroll
        for (int jj = 0; jj < 4; jj++) {
            long hidx = ((long)(b * 16 + q4) * FOUR_D + n0 + tx * 4 + jj) * 4 + qp;
            U4h[hidx] = __float2half_rn(acc[i][jj]);
        }
    }
}

// ---------------- GEMM 128x64 tile body (two big fp32 outputs) ----------------
__device__ __forceinline__ void gemm128_body(
    const float* __restrict__ A, int lda,
    const float* __restrict__ Bm, int ldb,
    float* __restrict__ C, int ldc, const float* __restrict__ bias)
{
    __shared__ float As[16][132];
    __shared__ float Bs[16][68];
    const int m0 = blockIdx.y * 128;
    const int n0 = blockIdx.x * 64;
    const int tid = threadIdx.x;
    const int tx = tid & 15;
    const int ty = tid >> 4;
    const int arow = tid >> 1, ak = (tid & 1) * 8;
    const int brow = tid >> 2, bk = (tid & 3) * 4;

    float acc[8][4];
#pragma unroll
    for (int i = 0; i < 8; i++)
#pragma unroll
        for (int j = 0; j < 4; j++) acc[i][j] = 0.f;

    for (int k0 = 0; k0 < 512; k0 += 16) {
        float4 a0 = *(const float4*)&A [(long)(m0 + arow) * lda + k0 + ak];
        float4 a1 = *(const float4*)&A [(long)(m0 + arow) * lda + k0 + ak + 4];
        float4 b4 = *(const float4*)&Bm[(long)(n0 + brow) * ldb + k0 + bk];
        __syncthreads();
        As[ak + 0][arow] = a0.x; As[ak + 1][arow] = a0.y;
        As[ak + 2][arow] = a0.z; As[ak + 3][arow] = a0.w;
        As[ak + 4][arow] = a1.x; As[ak + 5][arow] = a1.y;
        As[ak + 6][arow] = a1.z; As[ak + 7][arow] = a1.w;
        Bs[bk + 0][brow] = b4.x; Bs[bk + 1][brow] = b4.y;
        Bs[bk + 2][brow] = b4.z; Bs[bk + 3][brow] = b4.w;
        __syncthreads();
#pragma unroll
        for (int kk = 0; kk < 16; kk++) {
            float4 av0 = *(const float4*)&As[kk][ty * 8];
            float4 av1 = *(const float4*)&As[kk][ty * 8 + 4];
            float4 bv  = *(const float4*)&Bs[kk][tx * 4];
            acc[0][0] += av0.x * bv.x; acc[0][1] += av0.x * bv.y;
            acc[0][2] += av0.x * bv.z; acc[0][3] += av0.x * bv.w;
            acc[1][0] += av0.y * bv.x; acc[1][1] += av0.y * bv.y;
            acc[1][2] += av0.y * bv.z; acc[1][3] += av0.y * bv.w;
            acc[2][0] += av0.z * bv.x; acc[2][1] += av0.z * bv.y;
            acc[2][2] += av0.z * bv.z; acc[2][3] += av0.z * bv.w;
            acc[3][0] += av0.w * bv.x; acc[3][1] += av0.w * bv.y;
            acc[3][2] += av0.w * bv.z; acc[3][3] += av0.w * bv.w;
            acc[4][0] += av1.x * bv.x; acc[4][1] += av1.x * bv.y;
            acc[4][2] += av1.x * bv.z; acc[4][3] += av1.x * bv.w;
            acc[5][0] += av1.y * bv.x; acc[5][1] += av1.y * bv.y;
            acc[5][2] += av1.y * bv.z; acc[5][3] += av1.y * bv.w;
            acc[6][0] += av1.z * bv.x; acc[6][1] += av1.z * bv.y;
            acc[6][2] += av1.z * bv.z; acc[6][3] += av1.z * bv.w;
            acc[7][0] += av1.w * bv.x; acc[7][1] += av1.w * bv.y;
            acc[7][2] += av1.w * bv.z; acc[7][3] += av1.w * bv.w;
        }
    }

    float4 bb = make_float4(0.f, 0.f, 0.f, 0.f);
    if (bias) bb = *(const float4*)&bias[n0 + tx * 4];
#pragma unroll
    for (int i = 0; i < 8; i++) {
        long row = m0 + ty * 8 + i;
        float4 o;
        o.x = acc[i][0] + bb.x; o.y = acc[i][1] + bb.y;
        o.z = acc[i][2] + bb.z; o.w = acc[i][3] + bb.w;
        *(float4*)&C[row * ldc + n0 + tx * 4] = o;
    }
}

__global__ void __launch_bounds__(256)
k_gemm_spre(const float* __restrict__ H_p, const float* __restrict__ Wa,
            const float* __restrict__ ba) {
    gemm128_body(H_p, TWO_D, Wa, TWO_D, d_Spre, Dh, ba);
}
__global__ void __launch_bounds__(256)
k_gemm_gp(const float* __restrict__ H_p, const float* __restrict__ W_ih) {
    gemm128_body(H_p, TWO_D, W_ih, LDW, d_Gp, FOUR_D, d_bsum);
}

// ---------------- sequential MatchLSTM: 2-CTA cluster per batch element ----------
// Cluster choreography IDENTICAL to the passing R6 kernel: phases 1-2 on d-half,
// partial-logit exchange (stc_f32) + sync#1; phase 4 on j-half jp = r*256+tid with
// gate exchange (stc_f32x2) + sync#2; phase 5 redundant (h,c replicated).
// New vs R6: HFMA2 inner products (h cached as fp16, fp32 flush per 16 iters) and
// tanh.approx in attention. LSTM cell stays precise tanh/sigmoid.
__device__ __forceinline__ float sigmoidf_(float x) { return 1.f / (1.f + expf(-x)); }

__global__ __launch_bounds__(256, 1) __cluster_dims__(2, 1, 1)
void seq_kernel(const float* __restrict__ h0,
                const float* __restrict__ c0,
                const float* __restrict__ alpha_w,
                const float* __restrict__ alpha_b,
                float* __restrict__ out)
{
    __shared__ __align__(16) float  h_s[Dh];
    __shared__ __align__(16) __half h_h[Dh];
    __shared__ __align__(16) float  c_s[Dh];
    __shared__ __align__(16) float  s_s[128];          // local d-half
    __shared__ __align__(16) float  s_part[2][128];
    __shared__ __align__(16) float  gates_s[FOUR_D];   // full (peer fills other half)
    __shared__ __align__(16) float  logit_part[2][Qn];
    __shared__ __align__(16) float  alpha_s[Qn];
    __shared__ __align__(16) float  aw_s[Dh];

    const int tid  = threadIdx.x;
    const int warp = tid >> 5;
    const int lane = tid & 31;
    const unsigned rank = ctarank_u32();
    const unsigned peer = 1u - rank;
    const int r = (int)rank;
    const int b = blockIdx.x >> 1;
    const float ab = alpha_b[0];

    const unsigned gates_peer = mapa_u32(smem_u32(gates_s), peer);
    const unsigned logit_peer = mapa_u32(smem_u32(&logit_part[r][0]), peer);

    const __half* gah = (const __half*)d_ga4 + (long)b * Qn * Dh;
    const uint4*  u4b = d_U4 + (long)b * 16 * 512;
    const __half2 h2z = __float2half2_rn(0.f);

    aw_s[tid] = alpha_w[tid];
    float hv0 = h0[b * Dh + tid];
    h_s[tid] = hv0;
    h_h[tid] = __float2half_rn(hv0);
    c_s[tid] = c0[b * Dh + tid];
    CLUSTER_SYNC();   // both CTAs initialized before any DSMEM traffic

    for (int t = 0; t < Pn; t++) {
        // ---- phase 1: s for local d-half via HFMA2; thread (ec, dd) ----
        {
            const int dd = tid & 127, ec = tid >> 7;   // ec in {0,1}
            const int d = 128 * r + dd;
            const uint2* wb  = d_Wb4 + ec * 32 * 256 + d;
            const uint2* hhp = (const uint2*)h_h + ec * 32;   // 4 halves per entry
            float accf = 0.f;
            __half2 acc = h2z;
#pragma unroll
            for (int g = 0; g < 4; g++) {
#pragma unroll
                for (int i = 0; i < 8; i++) {
                    const int e4 = g * 8 + i;
                    uint2 w  = wb[e4 * 256];
                    uint2 hh = hhp[e4];
                    acc = __hfma2(u2h2(w.x), u2h2(hh.x), acc);
                    acc = __hfma2(u2h2(w.y), u2h2(hh.y), acc);
                }
                float2 f = __half22float2(acc);
                accf += f.x + f.y;
                acc = h2z;
            }
            s_part[ec][dd] = accf;
        }
        __syncthreads();
        if (tid < 128)
            s_s[tid] = d_Spre[((long)(t * Bn + b)) * Dh + 128 * r + tid]
                     + s_part[0][tid] + s_part[1][tid];
        __syncthreads();

        // ---- phase 2: partial logits over local d-half; 8 warps x 8 q ----
#pragma unroll
        for (int qi = 0; qi < 8; qi++) {
            const int q  = warp * 8 + qi;
            const int dl = lane * 4;
            const int dg = 128 * r + dl;
            uint2 g = *(const uint2*)&gah[(long)q * Dh + dg];
            float2 g0 = h22f2(g.x), g1 = h22f2(g.y);
            float sum =
                tanh_a(g0.x + s_s[dl    ]) * aw_s[dg    ] +
                tanh_a(g0.y + s_s[dl + 1]) * aw_s[dg + 1] +
                tanh_a(g1.x + s_s[dl + 2]) * aw_s[dg + 2] +
                tanh_a(g1.y + s_s[dl + 3]) * aw_s[dg + 3];
#pragma unroll
            for (int o = 16; o > 0; o >>= 1)
                sum += __shfl_xor_sync(0xffffffffu, sum, o);
            if (lane == 0) {
                logit_part[r][q] = sum;
                stc_f32(logit_peer + q * 4, sum);
            }
        }
        CLUSTER_SYNC();   // #1: partial logits visible in both CTAs

        // ---- phase 3: redundant softmax over 64 q (warp 0) ----
        if (warp == 0) {
            float l0 = logit_part[0][lane]      + logit_part[1][lane]      + ab;
            float l1 = logit_part[0][lane + 32] + logit_part[1][lane + 32] + ab;
            float m = fmaxf(l0, l1);
#pragma unroll
            for (int o = 16; o > 0; o >>= 1)
                m = fmaxf(m, __shfl_xor_sync(0xffffffffu, m, o));
            float e0 = expf(l0 - m), e1 = expf(l1 - m);
            float ssum = e0 + e1;
#pragma unroll
            for (int o = 16; o > 0; o >>= 1)
                ssum += __shfl_xor_sync(0xffffffffu, ssum, o);
            float inv = 1.f / ssum;
            alpha_s[lane]      = e0 * inv;
            alpha_s[lane + 32] = e1 * inv;
        }
        __syncthreads();

        // ---- phase 4: gates for local j-half (jp = r*256 + tid), HFMA2 ----
        {
            const int jp = r * 256 + tid;
            float2 gp2 = *(const float2*)&d_Gp[((long)(t * Bn + b)) * FOUR_D + 2 * jp];
            float g0 = gp2.x, g1 = gp2.y;
            const uint2* hhp = (const uint2*)h_h;
            __half2 a0 = h2z, a1 = h2z;
#pragma unroll
            for (int grp = 0; grp < 4; grp++) {
#pragma unroll
                for (int i = 0; i < 16; i++) {
                    const int e4 = grp * 16 + i;
                    uint4 w  = d_Wh4[e4 * 512 + jp];
                    uint2 hh = hhp[e4];
                    a0 = __hfma2(u2h2(w.x), u2h2(hh.x), a0);
                    a0 = __hfma2(u2h2(w.y), u2h2(hh.y), a0);
                    a1 = __hfma2(u2h2(w.z), u2h2(hh.x), a1);
                    a1 = __hfma2(u2h2(w.w), u2h2(hh.y), a1);
                }
                float2 f0 = __half22float2(a0); g0 += f0.x + f0.y; a0 = h2z;
                float2 f1 = __half22float2(a1); g1 += f1.x + f1.y; a1 = h2z;
            }
            // U·alpha in fp32 (16 iters)
#pragma unroll 4
            for (int q4 = 0; q4 < 16; q4++) {
                uint4 w = u4b[q4 * 512 + jp];
                float4 av = *(const float4*)&alpha_s[4 * q4];
                float2 p;
                p = h22f2(w.x); g0 += av.x * p.x + av.y * p.y;
                p = h22f2(w.y); g0 += av.z * p.x + av.w * p.y;
                p = h22f2(w.z); g1 += av.x * p.x + av.y * p.y;
                p = h22f2(w.w); g1 += av.z * p.x + av.w * p.y;
            }
            gates_s[2 * jp]     = g0;                      // local
            gates_s[2 * jp + 1] = g1;
            stc_f32x2(gates_peer + (2 * jp) * 4, g0, g1);  // peer's same slots
        }
        CLUSTER_SYNC();   // #2: full gate vector in both CTAs

        // ---- phase 5: redundant LSTM pointwise; d = tid (h,c stay replicated) ----
        {
            float ig = gates_s[tid];
            float fg = gates_s[Dh + tid];
            float gg = gates_s[2 * Dh + tid];
            float og = gates_s[3 * Dh + tid];
            float cn = sigmoidf_(fg) * c_s[tid] + sigmoidf_(ig) * tanhf(gg);
            float hn = sigmoidf_(og) * tanhf(cn);
            c_s[tid] = cn;
            h_s[tid] = hn;
            h_h[tid] = __float2half_rn(hn);
            if ((tid >> 7) == r)                      // each CTA writes its d-half
                out[((long)t * Bn + b) * Dh + tid] = hn;
        }
        __syncthreads();   // h_h/c_s settled before next step's phase 1/4 reads
    }
}

// ---------------- launch: kernel launches ONLY ----------------
extern "C" void kernel_launch(void* const* d_in, const int* in_sizes, int n_in,
                              void* d_out, int out_size)
{
    const float* H_p     = (const float*)d_in[0];
    const float* h_ri    = (const float*)d_in[1];
    const float* H_q     = (const float*)d_in[2];
    const float* hidden  = (const float*)d_in[3];
    const float* Wa      = (const float*)d_in[4];
    const float* ba      = (const float*)d_in[5];
    const float* Wb      = (const float*)d_in[6];
    const float* Wg      = (const float*)d_in[7];
    const float* alpha_w = (const float*)d_in[8];
    const float* alpha_b = (const float*)d_in[9];
    const float* W_ih    = (const float*)d_in[10];
    const float* W_hh    = (const float*)d_in[11];
    const float* b_ih    = (const float*)d_in[12];
    const float* b_hh    = (const float*)d_in[13];
    float* out = (float*)d_out;

    prep_kernel<<<256, 256>>>(b_ih, b_hh, W_hh, Wb);

    k_gemm_ga  <<<dim3(Dh / 64,     (Qn * Bn) / 64,  1),  256>>>(H_q, Wg);
    k_gemm_spre<<<dim3(Dh / 64,     (Pn * Bn) / 128, 1),  256>>>(H_p, Wa, ba);
    k_gemm_gp  <<<dim3(FOUR_D / 64, (Pn * Bn) / 128, 1),  256>>>(H_p, W_ih);
    k_gemm_u   <<<dim3(FOUR_D / 64, 1,               Qn), 256>>>(H_q, W_ih);

    seq_kernel<<<2 * Bn, 256>>>(h_ri, hidden, alpha_w, alpha_b, out);
}

// round 10
// speedup vs baseline: 3.3961x; 1.1834x over previous
#include <cuda_runtime.h>
#include <cuda_fp16.h>
#include <math.h>

// Problem dims (fixed by the reference)
#define Dh     256
#define Qn     64
#define Pn     128
#define Bn     64
#define TWO_D  512
#define FOUR_D 1024
#define LDW    33280   // (Q+1)*2D, row stride of W_ih

// ---------------- scratch (device globals: no allocation allowed) ----------------
__device__ float d_Spre[Pn * Bn * Dh];            //  8 MB
__device__ float d_Gp  [Pn * Bn * FOUR_D];        // 32 MB (+ b_ih+b_hh)
__device__ float d_bsum[FOUR_D];

// fp16 packed recurrent streams
__device__ uint4 d_ga4 [Bn * Qn * Dh / 8];        //  2 MB  gah[b][q][d]
__device__ uint4 d_Wh4 [64 * 512];                // 512 KB Wh4[e4][jp][..]
__device__ uint2 d_Wb4 [64 * 256];                // 128 KB Wb4[e4][d][4e]
__device__ uint4 d_U4  [Bn * 16 * 512];           //  8 MB  U4[b][q4][jp][..]

__device__ __forceinline__ float2 h22f2(unsigned u) {
    __half2 h = *reinterpret_cast<__half2*>(&u);
    return __half22float2(h);
}
__device__ __forceinline__ __half2 u2h2(unsigned u) {
    return *reinterpret_cast<__half2*>(&u);
}
__device__ __forceinline__ float tanh_a(float x) {
    float y; asm("tanh.approx.f32 %0, %1;" : "=f"(y) : "f"(x)); return y;
}

// ---------------- cluster helpers (proven R6/R9 pattern) ----------------
__device__ __forceinline__ unsigned smem_u32(const void* p) {
    unsigned a;
    asm("{ .reg .u64 t; cvta.to.shared.u64 t, %1; cvt.u32.u64 %0, t; }"
        : "=r"(a) : "l"(p));
    return a;
}
__device__ __forceinline__ unsigned mapa_u32(unsigned addr, unsigned rank) {
    unsigned r;
    asm("mapa.shared::cluster.u32 %0, %1, %2;" : "=r"(r) : "r"(addr), "r"(rank));
    return r;
}
__device__ __forceinline__ void stc_f32(unsigned addr, float v) {
    asm volatile("st.shared::cluster.f32 [%0], %1;" :: "r"(addr), "f"(v) : "memory");
}
__device__ __forceinline__ void stc_f32x2(unsigned addr, float v0, float v1) {
    asm volatile("st.shared::cluster.v2.f32 [%0], {%1, %2};"
                 :: "r"(addr), "f"(v0), "f"(v1) : "memory");
}
__device__ __forceinline__ unsigned ctarank_u32() {
    unsigned r; asm("mov.u32 %0, %%cluster_ctarank;" : "=r"(r)); return r;
}
#define CLUSTER_SYNC() do {                                          \
    asm volatile("barrier.cluster.arrive.aligned;" ::: "memory");    \
    asm volatile("barrier.cluster.wait.aligned;"   ::: "memory");    \
} while (0)

// ---------------- GEMM 64x64 body (proven; now a function of m0,n0) ------------
__device__ __forceinline__ void gemm64_body(
    int m0, int n0,
    const float* __restrict__ A, int lda,
    const float* __restrict__ Bm, int ldb,
    float acc[4][4], int tid)
{
    __shared__ float As64[16][68];
    __shared__ float Bs64[16][68];
    const int tx = tid & 15;
    const int ty = tid >> 4;
    const int lr = tid >> 2;
    const int lk = (tid & 3) * 4;

#pragma unroll
    for (int i = 0; i < 4; i++)
#pragma unroll
        for (int j = 0; j < 4; j++) acc[i][j] = 0.f;

    for (int k0 = 0; k0 < 512; k0 += 16) {
        float4 a4 = *(const float4*)&A [(long)(m0 + lr) * lda + k0 + lk];
        float4 b4 = *(const float4*)&Bm[(long)(n0 + lr) * ldb + k0 + lk];
        __syncthreads();
        As64[lk + 0][lr] = a4.x; As64[lk + 1][lr] = a4.y;
        As64[lk + 2][lr] = a4.z; As64[lk + 3][lr] = a4.w;
        Bs64[lk + 0][lr] = b4.x; Bs64[lk + 1][lr] = b4.y;
        Bs64[lk + 2][lr] = b4.z; Bs64[lk + 3][lr] = b4.w;
        __syncthreads();
#pragma unroll
        for (int kk = 0; kk < 16; kk++) {
            float4 av = *(const float4*)&As64[kk][ty * 4];
            float4 bv = *(const float4*)&Bs64[kk][tx * 4];
            acc[0][0] += av.x * bv.x; acc[0][1] += av.x * bv.y;
            acc[0][2] += av.x * bv.z; acc[0][3] += av.x * bv.w;
            acc[1][0] += av.y * bv.x; acc[1][1] += av.y * bv.y;
            acc[1][2] += av.y * bv.z; acc[1][3] += av.y * bv.w;
            acc[2][0] += av.z * bv.x; acc[2][1] += av.z * bv.y;
            acc[2][2] += av.z * bv.z; acc[2][3] += av.z * bv.w;
            acc[3][0] += av.w * bv.x; acc[3][1] += av.w * bv.y;
            acc[3][2] += av.w * bv.z; acc[3][3] += av.w * bv.w;
        }
    }
}

// ---------------- GEMM 128x128 body, 8x8 per thread (fp32) ----------------------
__device__ __forceinline__ void gemm128x128_body(
    int m0, int n0,
    const float* __restrict__ A, int lda,
    const float* __restrict__ Bm, int ldb,
    float* __restrict__ C, int ldc, const float* __restrict__ bias, int tid)
{
    __shared__ float As[16][132];
    __shared__ float Bs[16][132];
    const int tx = tid & 15;          // 8 cols each
    const int ty = tid >> 4;          // 8 rows each
    const int lrow = tid >> 1;        // 0..127
    const int lk   = (tid & 1) * 8;   // 0 or 8

    float acc[8][8];
#pragma unroll
    for (int i = 0; i < 8; i++)
#pragma unroll
        for (int j = 0; j < 8; j++) acc[i][j] = 0.f;

    for (int k0 = 0; k0 < 512; k0 += 16) {
        float4 a0 = *(const float4*)&A [(long)(m0 + lrow) * lda + k0 + lk];
        float4 a1 = *(const float4*)&A [(long)(m0 + lrow) * lda + k0 + lk + 4];
        float4 b0 = *(const float4*)&Bm[(long)(n0 + lrow) * ldb + k0 + lk];
        float4 b1 = *(const float4*)&Bm[(long)(n0 + lrow) * ldb + k0 + lk + 4];
        __syncthreads();
        As[lk + 0][lrow] = a0.x; As[lk + 1][lrow] = a0.y;
        As[lk + 2][lrow] = a0.z; As[lk + 3][lrow] = a0.w;
        As[lk + 4][lrow] = a1.x; As[lk + 5][lrow] = a1.y;
        As[lk + 6][lrow] = a1.z; As[lk + 7][lrow] = a1.w;
        Bs[lk + 0][lrow] = b0.x; Bs[lk + 1][lrow] = b0.y;
        Bs[lk + 2][lrow] = b0.z; Bs[lk + 3][lrow] = b0.w;
        Bs[lk + 4][lrow] = b1.x; Bs[lk + 5][lrow] = b1.y;
        Bs[lk + 6][lrow] = b1.z; Bs[lk + 7][lrow] = b1.w;
        __syncthreads();
#pragma unroll
        for (int kk = 0; kk < 16; kk++) {
            float4 av0 = *(const float4*)&As[kk][ty * 8];
            float4 av1 = *(const float4*)&As[kk][ty * 8 + 4];
            float4 bv0 = *(const float4*)&Bs[kk][tx * 8];
            float4 bv1 = *(const float4*)&Bs[kk][tx * 8 + 4];
            float a_[8] = {av0.x, av0.y, av0.z, av0.w, av1.x, av1.y, av1.z, av1.w};
            float b_[8] = {bv0.x, bv0.y, bv0.z, bv0.w, bv1.x, bv1.y, bv1.z, bv1.w};
#pragma unroll
            for (int i = 0; i < 8; i++)
#pragma unroll
                for (int j = 0; j < 8; j++)
                    acc[i][j] += a_[i] * b_[j];
        }
    }

    float bb[8];
#pragma unroll
    for (int j = 0; j < 8; j++) bb[j] = bias ? bias[n0 + tx * 8 + j] : 0.f;
#pragma unroll
    for (int i = 0; i < 8; i++) {
        long row = m0 + ty * 8 + i;
        float4 o0, o1;
        o0.x = acc[i][0] + bb[0]; o0.y = acc[i][1] + bb[1];
        o0.z = acc[i][2] + bb[2]; o0.w = acc[i][3] + bb[3];
        o1.x = acc[i][4] + bb[4]; o1.y = acc[i][5] + bb[5];
        o1.z = acc[i][6] + bb[6]; o1.w = acc[i][7] + bb[7];
        *(float4*)&C[row * ldc + n0 + tx * 8]     = o0;
        *(float4*)&C[row * ldc + n0 + tx * 8 + 4] = o1;
    }
}

// ---------------- front kernel: prep (256 blk) + ga (256 blk) + spre (128 blk) --
__global__ void __launch_bounds__(256)
k_front(const float* __restrict__ b_ih, const float* __restrict__ b_hh,
        const float* __restrict__ W_hh, const float* __restrict__ Wb,
        const float* __restrict__ H_q,  const float* __restrict__ Wg,
        const float* __restrict__ H_p,  const float* __restrict__ Wa,
        const float* __restrict__ ba)
{
    const int bx = blockIdx.x;
    const int tid = threadIdx.x;

    if (bx < 256) {
        // ---- prep: pack W_hh, Wb to fp16; bias sum ----
        int idx = bx * 256 + tid;
        {
            int e4 = idx & 63, j = idx >> 6;
            float4 w = *(const float4*)&W_hh[j * Dh + e4 * 4];
            __half2 h01 = __floats2half2_rn(w.x, w.y);
            __half2 h23 = __floats2half2_rn(w.z, w.w);
            uint2 v;
            v.x = *reinterpret_cast<unsigned*>(&h01);
            v.y = *reinterpret_cast<unsigned*>(&h23);
            ((uint2*)d_Wh4)[e4 * 1024 + j] = v;
        }
        if (idx < 16384) {
            int e4 = idx & 63, d = idx >> 6;
            float4 w = *(const float4*)&Wb[d * Dh + e4 * 4];
            __half2 h01 = __floats2half2_rn(w.x, w.y);
            __half2 h23 = __floats2half2_rn(w.z, w.w);
            uint2 v;
            v.x = *reinterpret_cast<unsigned*>(&h01);
            v.y = *reinterpret_cast<unsigned*>(&h23);
            d_Wb4[e4 * 256 + d] = v;
        }
        if (idx < FOUR_D) d_bsum[idx] = b_ih[idx] + b_hh[idx];
    } else if (bx < 512) {
        // ---- ga = H_q @ Wg^T -> half gah[b][q][d] ----
        const int t = bx - 256;
        const int n0 = (t & 3) * 64, m0 = (t >> 2) * 64;
        float acc[4][4];
        gemm64_body(m0, n0, H_q, TWO_D, Wg, TWO_D, acc, tid);
        __half* gah = (__half*)d_ga4;
        const int tx = tid & 15, ty = tid >> 4;
#pragma unroll
        for (int i = 0; i < 4; i++) {
            int m = m0 + ty * 4 + i;       // m = q*64 + b
            int q = m >> 6, b = m & 63;
            __half2 p01 = __floats2half2_rn(acc[i][0], acc[i][1]);
            __half2 p23 = __floats2half2_rn(acc[i][2], acc[i][3]);
            uint2 v;
            v.x = *reinterpret_cast<unsigned*>(&p01);
            v.y = *reinterpret_cast<unsigned*>(&p23);
            *(uint2*)&gah[((b * Qn + q) * Dh) + n0 + tx * 4] = v;
        }
    } else {
        // ---- Spre = H_p @ Wa^T + ba (fp32, 128x128 tiles) ----
        const int t = bx - 512;
        const int n0 = (t & 1) * 128, m0 = (t >> 1) * 128;
        gemm128x128_body(m0, n0, H_p, TWO_D, Wa, TWO_D, d_Spre, Dh, ba, tid);
    }
}

// ---------------- gp = H_p @ W_ih[:, :2D]^T + bsum (128x128 tiles) --------------
__global__ void __launch_bounds__(256)
k_gemm_gp(const float* __restrict__ H_p, const float* __restrict__ W_ih) {
    gemm128x128_body(blockIdx.y * 128, blockIdx.x * 128,
                     H_p, TWO_D, W_ih, LDW, d_Gp, FOUR_D, d_bsum, threadIdx.x);
}

// ---------------- U[q] = H_q[q] @ W_ih slice^T -> half U4 -----------------------
__global__ void __launch_bounds__(256)
k_gemm_u(const float* __restrict__ Aq, const float* __restrict__ W_ih) {
    const int q = blockIdx.z;
    const int m0 = 0, n0 = blockIdx.x * 64;
    float acc[4][4];
    gemm64_body(m0, n0, Aq + (long)q * Bn * TWO_D, TWO_D,
                W_ih + TWO_D + (long)q * TWO_D, LDW, acc, threadIdx.x);
    __half* U4h = (__half*)d_U4;
    const int tx = threadIdx.x & 15, ty = threadIdx.x >> 4;
    const int q4 = q >> 2, qp = q & 3;
#pragma unroll
    for (int i = 0; i < 4; i++) {
        int b = m0 + ty * 4 + i;
#pragma unroll
        for (int jj = 0; jj < 4; jj++) {
            long hidx = ((long)(b * 16 + q4) * FOUR_D + n0 + tx * 4 + jj) * 4 + qp;
            U4h[hidx] = __float2half_rn(acc[i][jj]);
        }
    }
}

// ---------------- sequential MatchLSTM: 2-CTA cluster per batch (R9 choreography,
// + step-top prefetch of Gp/Spre, + split HFMA2/FFMA accumulation chains) -------
__device__ __forceinline__ float sigmoidf_(float x) { return 1.f / (1.f + expf(-x)); }

__global__ __launch_bounds__(256, 1) __cluster_dims__(2, 1, 1)
void seq_kernel(const float* __restrict__ h0,
                const float* __restrict__ c0,
                const float* __restrict__ alpha_w,
                const float* __restrict__ alpha_b,
                float* __restrict__ out)
{
    __shared__ __align__(16) float  h_s[Dh];
    __shared__ __align__(16) __half h_h[Dh];
    __shared__ __align__(16) float  c_s[Dh];
    __shared__ __align__(16) float  s_s[128];
    __shared__ __align__(16) float  s_part[2][128];
    __shared__ __align__(16) float  gates_s[FOUR_D];
    __shared__ __align__(16) float  logit_part[2][Qn];
    __shared__ __align__(16) float  alpha_s[Qn];
    __shared__ __align__(16) float  aw_s[Dh];

    const int tid  = threadIdx.x;
    const int warp = tid >> 5;
    const int lane = tid & 31;
    const unsigned rank = ctarank_u32();
    const unsigned peer = 1u - rank;
    const int r = (int)rank;
    const int b = blockIdx.x >> 1;
    const float ab = alpha_b[0];

    const unsigned gates_peer = mapa_u32(smem_u32(gates_s), peer);
    const unsigned logit_peer = mapa_u32(smem_u32(&logit_part[r][0]), peer);

    const __half* gah = (const __half*)d_ga4 + (long)b * Qn * Dh;
    const uint4*  u4b = d_U4 + (long)b * 16 * 512;
    const __half2 h2z = __float2half2_rn(0.f);
    const int jp = r * 256 + tid;           // phase-4 column pair (constant)
    const int dd = tid & 127, ec = tid >> 7;

    aw_s[tid] = alpha_w[tid];
    float hv0 = h0[b * Dh + tid];
    h_s[tid] = hv0;
    h_h[tid] = __float2half_rn(hv0);
    c_s[tid] = c0[b * Dh + tid];
    CLUSTER_SYNC();

    for (int t = 0; t < Pn; t++) {
        // ---- step-top prefetch (state-independent; consumed late) ----
        float2 gp_pre = *(const float2*)&d_Gp[((long)(t * Bn + b)) * FOUR_D + 2 * jp];
        float spre_pre = 0.f;
        if (tid < 128)
            spre_pre = d_Spre[((long)(t * Bn + b)) * Dh + 128 * r + tid];

        // ---- phase 1: s for local d-half via HFMA2, two chains ----
        {
            const int d = 128 * r + dd;
            const uint2* wb  = d_Wb4 + ec * 32 * 256 + d;
            const uint2* hhp = (const uint2*)h_h + ec * 32;
            float accf = 0.f;
            __half2 aA = h2z, aB = h2z;
#pragma unroll
            for (int o = 0; o < 2; o++) {
#pragma unroll
                for (int i = 0; i < 8; i++) {
                    const int eA = o * 8 + i;        // 0..15
                    const int eB = eA + 16;          // 16..31
                    uint2 wA = wb[eA * 256], wB = wb[eB * 256];
                    uint2 hA = hhp[eA],     hB = hhp[eB];
                    aA = __hfma2(u2h2(wA.x), u2h2(hA.x), aA);
                    aA = __hfma2(u2h2(wA.y), u2h2(hA.y), aA);
                    aB = __hfma2(u2h2(wB.x), u2h2(hB.x), aB);
                    aB = __hfma2(u2h2(wB.y), u2h2(hB.y), aB);
                }
                float2 fA = __half22float2(aA); accf += fA.x + fA.y; aA = h2z;
                float2 fB = __half22float2(aB); accf += fB.x + fB.y; aB = h2z;
            }
            s_part[ec][dd] = accf;
        }
        __syncthreads();
        if (tid < 128)
            s_s[tid] = spre_pre + s_part[0][tid] + s_part[1][tid];
        __syncthreads();

        // ---- phase 2: partial logits; gah loads hoisted for MLP=8 ----
        {
            const int dl = lane * 4;
            const int dg = 128 * r + dl;
            uint2 gq[8];
#pragma unroll
            for (int qi = 0; qi < 8; qi++)
                gq[qi] = *(const uint2*)&gah[(long)(warp * 8 + qi) * Dh + dg];
            const float s0 = s_s[dl], s1 = s_s[dl + 1],
                        s2 = s_s[dl + 2], s3 = s_s[dl + 3];
            const float w0 = aw_s[dg], w1 = aw_s[dg + 1],
                        w2 = aw_s[dg + 2], w3 = aw_s[dg + 3];
#pragma unroll
            for (int qi = 0; qi < 8; qi++) {
                const int q = warp * 8 + qi;
                float2 g0 = h22f2(gq[qi].x), g1 = h22f2(gq[qi].y);
                float sum = tanh_a(g0.x + s0) * w0 + tanh_a(g0.y + s1) * w1 +
                            tanh_a(g1.x + s2) * w2 + tanh_a(g1.y + s3) * w3;
#pragma unroll
                for (int o = 16; o > 0; o >>= 1)
                    sum += __shfl_xor_sync(0xffffffffu, sum, o);
                if (lane == 0) {
                    logit_part[r][q] = sum;
                    stc_f32(logit_peer + q * 4, sum);
                }
            }
        }
        CLUSTER_SYNC();   // #1: partial logits visible in both CTAs

        // ---- phase 3: redundant softmax over 64 q (warp 0) ----
        if (warp == 0) {
            float l0 = logit_part[0][lane]      + logit_part[1][lane]      + ab;
            float l1 = logit_part[0][lane + 32] + logit_part[1][lane + 32] + ab;
            float m = fmaxf(l0, l1);
#pragma unroll
            for (int o = 16; o > 0; o >>= 1)
                m = fmaxf(m, __shfl_xor_sync(0xffffffffu, m, o));
            float e0 = expf(l0 - m), e1 = expf(l1 - m);
            float ssum = e0 + e1;
#pragma unroll
            for (int o = 16; o > 0; o >>= 1)
                ssum += __shfl_xor_sync(0xffffffffu, ssum, o);
            float inv = 1.f / ssum;
            alpha_s[lane]      = e0 * inv;
            alpha_s[lane + 32] = e1 * inv;
        }
        __syncthreads();

        // ---- phase 4: gates for local j-half; 4 HFMA2 chains + 2 FFMA chains ----
        {
            float g0 = gp_pre.x, g1 = gp_pre.y;
            const uint2* hhp = (const uint2*)h_h;
            __half2 a0A = h2z, a1A = h2z, a0B = h2z, a1B = h2z;
#pragma unroll
            for (int o = 0; o < 2; o++) {
#pragma unroll
                for (int i = 0; i < 16; i++) {
                    const int eA = o * 16 + i;       // 0..31
                    const int eB = eA + 32;          // 32..63
                    uint4 wA = d_Wh4[eA * 512 + jp];
                    uint4 wB = d_Wh4[eB * 512 + jp];
                    uint2 hA = hhp[eA], hB = hhp[eB];
                    a0A = __hfma2(u2h2(wA.x), u2h2(hA.x), a0A);
                    a0A = __hfma2(u2h2(wA.y), u2h2(hA.y), a0A);
                    a1A = __hfma2(u2h2(wA.z), u2h2(hA.x), a1A);
                    a1A = __hfma2(u2h2(wA.w), u2h2(hA.y), a1A);
                    a0B = __hfma2(u2h2(wB.x), u2h2(hB.x), a0B);
                    a0B = __hfma2(u2h2(wB.y), u2h2(hB.y), a0B);
                    a1B = __hfma2(u2h2(wB.z), u2h2(hB.x), a1B);
                    a1B = __hfma2(u2h2(wB.w), u2h2(hB.y), a1B);
                }
                float2 f;
                f = __half22float2(a0A); g0 += f.x + f.y; a0A = h2z;
                f = __half22float2(a1A); g1 += f.x + f.y; a1A = h2z;
                f = __half22float2(a0B); g0 += f.x + f.y; a0B = h2z;
                f = __half22float2(a1B); g1 += f.x + f.y; a1B = h2z;
            }
            // U·alpha in fp32, two chains
            float g0b = 0.f, g1b = 0.f;
#pragma unroll
            for (int q4 = 0; q4 < 8; q4++) {
                uint4 wA = u4b[q4 * 512 + jp];
                uint4 wB = u4b[(q4 + 8) * 512 + jp];
                float4 avA = *(const float4*)&alpha_s[4 * q4];
                float4 avB = *(const float4*)&alpha_s[4 * (q4 + 8)];
                float2 p;
                p = h22f2(wA.x); g0  += avA.x * p.x + avA.y * p.y;
                p = h22f2(wA.y); g0  += avA.z * p.x + avA.w * p.y;
                p = h22f2(wA.z); g1  += avA.x * p.x + avA.y * p.y;
                p = h22f2(wA.w); g1  += avA.z * p.x + avA.w * p.y;
                p = h22f2(wB.x); g0b += avB.x * p.x + avB.y * p.y;
                p = h22f2(wB.y); g0b += avB.z * p.x + avB.w * p.y;
                p = h22f2(wB.z); g1b += avB.x * p.x + avB.y * p.y;
                p = h22f2(wB.w); g1b += avB.z * p.x + avB.w * p.y;
            }
            g0 += g0b; g1 += g1b;
            gates_s[2 * jp]     = g0;
            gates_s[2 * jp + 1] = g1;
            stc_f32x2(gates_peer + (2 * jp) * 4, g0, g1);
        }
        CLUSTER_SYNC();   // #2: full gate vector in both CTAs

        // ---- phase 5: redundant LSTM pointwise (h,c stay replicated) ----
        {
            float ig = gates_s[tid];
            float fg = gates_s[Dh + tid];
            float gg = gates_s[2 * Dh + tid];
            float og = gates_s[3 * Dh + tid];
            float cn = sigmoidf_(fg) * c_s[tid] + sigmoidf_(ig) * tanhf(gg);
            float hn = sigmoidf_(og) * tanhf(cn);
            c_s[tid] = cn;
            h_s[tid] = hn;
            h_h[tid] = __float2half_rn(hn);
            if ((tid >> 7) == r)
                out[((long)t * Bn + b) * Dh + tid] = hn;
        }
        __syncthreads();
    }
}

// ---------------- launch: 4 kernels (front, gp, u, seq) ----------------
extern "C" void kernel_launch(void* const* d_in, const int* in_sizes, int n_in,
                              void* d_out, int out_size)
{
    const float* H_p     = (const float*)d_in[0];
    const float* h_ri    = (const float*)d_in[1];
    const float* H_q     = (const float*)d_in[2];
    const float* hidden  = (const float*)d_in[3];
    const float* Wa      = (const float*)d_in[4];
    const float* ba      = (const float*)d_in[5];
    const float* Wb      = (const float*)d_in[6];
    const float* Wg      = (const float*)d_in[7];
    const float* alpha_w = (const float*)d_in[8];
    const float* alpha_b = (const float*)d_in[9];
    const float* W_ih    = (const float*)d_in[10];
    const float* W_hh    = (const float*)d_in[11];
    const float* b_ih    = (const float*)d_in[12];
    const float* b_hh    = (const float*)d_in[13];
    float* out = (float*)d_out;

    // front: prep (256 blk) + ga (256 blk) + spre (128 blk)
    k_front<<<640, 256>>>(b_ih, b_hh, W_hh, Wb, H_q, Wg, H_p, Wa, ba);

    // gp: 128x128 tiles, needs d_bsum from front (stream-ordered)
    k_gemm_gp<<<dim3(FOUR_D / 128, (Pn * Bn) / 128), 256>>>(H_p, W_ih);

    // U: 64x64 tiles per q
    k_gemm_u<<<dim3(FOUR_D / 64, 1, Qn), 256>>>(H_q, W_ih);

    // sequential MatchLSTM: 64 clusters x 2 CTAs
    seq_kernel<<<2 * Bn, 256>>>(h_ri, hidden, alpha_w, alpha_b, out);
}